// round 11
// baseline (speedup 1.0000x reference)
#include <cuda_runtime.h>
#include <math.h>
#include <stdint.h>

// ---------------------------------------------------------------------------
// WindowAttention fused kernel, round 11: 384 threads (12 warps, occ +50% at
// same smem), merged single-phase attention (scores/softmax/attnv across all
// heads), all-MMA bf16-split math. 2 CTAs/SM.
// ---------------------------------------------------------------------------

#define NTOK   49
#define NCH    96
#define NHEADS 3
#define HDIM   32
#define ST     100
#define AST    50
#define CST    34
#define SCALEF 0.17677669529663687f
#define NTHR   384

#define BUF     (NTOK*ST)                  // 4900
#define OFF_A   0
#define OFF_B   (OFF_A + BUF)
#define OFF_C   (OFF_B + BUF)
#define OFF_D   (OFF_C + BUF)
#define OFF_RPB (OFF_D + BUF)              // 508
#define OFF_NQ  (OFF_RPB + 508)            // 96
#define OFF_NK  (OFF_NQ + 96)              // 96
#define OFF_E   (OFF_NK + 96)              // 4900 (scores span E+CAT)
#define OFF_CAT (OFF_E + BUF)              // 3264
#define SMEM_FLOATS (OFF_CAT + 3264)
#define SMEM_BYTES  (SMEM_FLOATS * 4)      // 113856

#define SCRH    2450                       // per-head score block (49*50)

#define FRAG_PER_G 2304
#define PROJ_FBASE (7 * FRAG_PER_G)
#define NFRAG      (PROJ_FBASE + 12 * 12 * 32)

__device__ uint4 g_wpack[NFRAG];

typedef unsigned long long u64;

__device__ __forceinline__ void fma2(u64& d, u64 a, u64 b) {
    asm("fma.rn.f32x2 %0,%1,%2,%0;" : "+l"(d) : "l"(a), "l"(b));
}
__device__ __forceinline__ float2 unp(u64 a) {
    float2 r; asm("mov.b64 {%0,%1},%2;" : "=f"(r.x), "=f"(r.y) : "l"(a)); return r;
}
__device__ __forceinline__ u64 lds64(const float* p) {
    return *reinterpret_cast<const u64*>(p);
}
__device__ __forceinline__ uint32_t cvtbf2(float h, float l) {
    uint32_t r; asm("cvt.rn.bf16x2.f32 %0, %1, %2;" : "=r"(r) : "f"(h), "f"(l)); return r;
}
__device__ __forceinline__ float blo2f(uint32_t p) { return __uint_as_float(p << 16); }
__device__ __forceinline__ float bhi2f(uint32_t p) { return __uint_as_float(p & 0xFFFF0000u); }

__device__ __forceinline__ void mma16(float d[4],
                                      uint32_t a0, uint32_t a1, uint32_t a2, uint32_t a3,
                                      uint32_t b0, uint32_t b1) {
    asm volatile("mma.sync.aligned.m16n8k16.row.col.f32.bf16.bf16.f32 "
                 "{%0,%1,%2,%3}, {%4,%5,%6,%7}, {%8,%9}, {%0,%1,%2,%3};"
                 : "+f"(d[0]), "+f"(d[1]), "+f"(d[2]), "+f"(d[3])
                 : "r"(a0), "r"(a1), "r"(a2), "r"(a3), "r"(b0), "r"(b1));
}

__device__ __forceinline__ void split2(float2 p, uint32_t& h, uint32_t& l) {
    h = cvtbf2(p.y, p.x);
    l = cvtbf2(p.y - bhi2f(h), p.x - blo2f(h));
}

// ---------------- prologue: pack weight B-fragments (slot n = slot*8+gid) ---
__global__ void prep_weights(const float* __restrict__ wq, const float* __restrict__ wk,
                             const float* __restrict__ wv, const float* __restrict__ w_ps,
                             const float* __restrict__ wq_sp, const float* __restrict__ wk_sp,
                             const float* __restrict__ w_pc, const float* __restrict__ w_proj)
{
    int idx = blockIdx.x * 256 + threadIdx.x;
    if (idx >= NFRAG) return;
    const float* Wt[8] = {wq, wk, wv, w_ps, wq_sp, wk_sp, w_pc, w_proj};
    int g, r;
    if (idx < PROJ_FBASE) { g = idx / FRAG_PER_G; r = idx % FRAG_PER_G; }
    else                  { g = 7; r = idx - PROJ_FBASE; }
    int kc   = r / 384;
    int rem  = r % 384;
    int slot = rem / 32;
    int lane = rem % 32;
    int gid = lane >> 2, tig = lane & 3;
    int kp = kc * 8 + tig;
    int n  = slot * 8 + gid;
    const float* W = Wt[g];
    float x0 = W[(2 * kp) * 96 + n];
    float x1 = W[(2 * kp + 1) * 96 + n];
    float y0 = W[(2 * kp + 8) * 96 + n];
    float y1 = W[(2 * kp + 9) * 96 + n];
    uint32_t b0h, b0l, b1h, b1l;
    split2(make_float2(x0, x1), b0h, b0l);
    split2(make_float2(y0, y1), b1h, b1l);
    g_wpack[idx] = make_uint4(b0h, b1h, b0l, b1l);
}

// ---- bf16-split GEMM, 12 warps: 4 m-tiles x 3 n-thirds (4 nt each) --------
__device__ __forceinline__ void gemm_bf16(const float* Xs, int fbase,
                                          const float* __restrict__ bias, float* Os,
                                          int warp, int lane)
{
    const int mt = warp & 3, nh = warp >> 2;       // nh in [0,3)
    const int m0 = mt * 16, n0 = nh * 32;
    const int gid = lane >> 2, tig = lane & 3;
    float d[4][4];
    #pragma unroll
    for (int i = 0; i < 4; i++) { d[i][0] = d[i][1] = d[i][2] = d[i][3] = 0.f; }
    const float* Xr0 = Xs + (m0 + gid) * ST;
    const float* Xr1 = Xs + (m0 + gid + 8) * ST;
    #pragma unroll
    for (int kc = 0; kc < 6; kc++) {
        const int kp = kc * 8 + tig;
        uint32_t a0h, a0l, a1h, a1l, a2h, a2l, a3h, a3l;
        split2(*reinterpret_cast<const float2*>(Xr0 + 2 * kp), a0h, a0l);
        split2(*reinterpret_cast<const float2*>(Xr1 + 2 * kp), a1h, a1l);
        split2(*reinterpret_cast<const float2*>(Xr0 + 2 * kp + 8), a2h, a2l);
        split2(*reinterpret_cast<const float2*>(Xr1 + 2 * kp + 8), a3h, a3l);
        const uint4* Bf = g_wpack + fbase + (kc * 12 + nh * 4) * 32 + lane;
        #pragma unroll
        for (int nt = 0; nt < 4; nt++) {
            uint4 w = Bf[nt * 32];
            mma16(d[nt], a0h, a1h, a2h, a3h, w.x, w.y);
            mma16(d[nt], a0h, a1h, a2h, a3h, w.z, w.w);
            mma16(d[nt], a0l, a1l, a2l, a3l, w.x, w.y);
        }
    }
    const int r0 = m0 + gid, r1 = m0 + gid + 8;
    #pragma unroll
    for (int nt = 0; nt < 4; nt++) {
        int n = n0 + nt * 8 + tig * 2;
        float bx = 0.f, by = 0.f;
        if (bias) { bx = bias[n]; by = bias[n + 1]; }
        if (r0 < NTOK) { float* o = Os + r0 * ST + n; o[0] = d[nt][0] + bx; o[1] = d[nt][1] + by; }
        if (r1 < NTOK) { float* o = Os + r1 * ST + n; o[0] = d[nt][2] + bx; o[1] = d[nt][3] + by; }
    }
}

// ---- final projection (K=192), 12 warps same tiling ------------------------
__device__ __forceinline__ void proj_bf16(const float* Sa, const float* Sb,
                                          const float* __restrict__ bias,
                                          float* __restrict__ og, int warp, int lane)
{
    const int mt = warp & 3, nh = warp >> 2;
    const int m0 = mt * 16, n0 = nh * 32;
    const int gid = lane >> 2, tig = lane & 3;
    float d[4][4];
    #pragma unroll
    for (int i = 0; i < 4; i++) { d[i][0] = d[i][1] = d[i][2] = d[i][3] = 0.f; }
    #pragma unroll
    for (int kc = 0; kc < 12; kc++) {
        const int kp = (kc % 6) * 8 + tig;
        const float* Xb = (kc < 6) ? Sa : Sb;
        const float* Xr0 = Xb + (m0 + gid) * ST;
        const float* Xr1 = Xb + (m0 + gid + 8) * ST;
        uint32_t a0h, a0l, a1h, a1l, a2h, a2l, a3h, a3l;
        split2(*reinterpret_cast<const float2*>(Xr0 + 2 * kp), a0h, a0l);
        split2(*reinterpret_cast<const float2*>(Xr1 + 2 * kp), a1h, a1l);
        split2(*reinterpret_cast<const float2*>(Xr0 + 2 * kp + 8), a2h, a2l);
        split2(*reinterpret_cast<const float2*>(Xr1 + 2 * kp + 8), a3h, a3l);
        const uint4* Bf = g_wpack + PROJ_FBASE + (kc * 12 + nh * 4) * 32 + lane;
        #pragma unroll
        for (int nt = 0; nt < 4; nt++) {
            uint4 w = Bf[nt * 32];
            mma16(d[nt], a0h, a1h, a2h, a3h, w.x, w.y);
            mma16(d[nt], a0h, a1h, a2h, a3h, w.z, w.w);
            mma16(d[nt], a0l, a1l, a2l, a3l, w.x, w.y);
        }
    }
    const int r0 = m0 + gid, r1 = m0 + gid + 8;
    #pragma unroll
    for (int nt = 0; nt < 4; nt++) {
        int n = n0 + nt * 8 + tig * 2;
        float bx = bias[n], by = bias[n + 1];
        if (r0 < NTOK) {
            float2 v = make_float2(d[nt][0] + bx, d[nt][1] + by);
            *reinterpret_cast<float2*>(og + r0 * NCH + n) = v;
        }
        if (r1 < NTOK) {
            float2 v = make_float2(d[nt][2] + bx, d[nt][3] + by);
            *reinterpret_cast<float2*>(og + r1 * NCH + n) = v;
        }
    }
}

// ---- scores (ALL heads): 24 slots over 12 warps ----------------------------
__device__ __forceinline__ void scores_mma(const float* Q, const float* K,
                                           float* SC, const float* RPB,
                                           int warp, int lane)
{
    const int gid = lane >> 2, tig = lane & 3;
    for (int slot = warp; slot < 24; slot += 12) {
        const int h = slot >> 3, q = slot & 7;
        const int m0 = (q >> 1) * 16, n0 = (q & 1) * 32;
        const int ch0 = h * HDIM;
        float* SCR = SC + h * SCRH;
        float d[4][4];
        #pragma unroll
        for (int i = 0; i < 4; i++) { d[i][0] = d[i][1] = d[i][2] = d[i][3] = 0.f; }
        const float* Qr0 = Q + (m0 + gid) * ST + ch0;
        const float* Qr1 = Qr0 + 8 * ST;
        #pragma unroll
        for (int kc = 0; kc < 2; kc++) {
            const int kp = kc * 8 + tig;
            uint32_t a0h, a0l, a1h, a1l, a2h, a2l, a3h, a3l;
            split2(*reinterpret_cast<const float2*>(Qr0 + 2 * kp), a0h, a0l);
            split2(*reinterpret_cast<const float2*>(Qr1 + 2 * kp), a1h, a1l);
            split2(*reinterpret_cast<const float2*>(Qr0 + 2 * kp + 8), a2h, a2l);
            split2(*reinterpret_cast<const float2*>(Qr1 + 2 * kp + 8), a3h, a3l);
            #pragma unroll
            for (int nt = 0; nt < 4; nt++) {
                const float* Kr = K + (n0 + nt * 8 + gid) * ST + ch0;
                uint32_t b0h, b0l, b1h, b1l;
                split2(*reinterpret_cast<const float2*>(Kr + 2 * kp), b0h, b0l);
                split2(*reinterpret_cast<const float2*>(Kr + 2 * kp + 8), b1h, b1l);
                mma16(d[nt], a0h, a1h, a2h, a3h, b0h, b1h);
                mma16(d[nt], a0h, a1h, a2h, a3h, b0l, b1l);
                mma16(d[nt], a0l, a1l, a2l, a3l, b0h, b1h);
            }
        }
        const int r0 = m0 + gid, r1 = r0 + 8;
        const int i0r = r0 / 7, i0c = r0 % 7;
        const int i1r = r1 / 7, i1c = r1 % 7;
        #pragma unroll
        for (int nt = 0; nt < 4; nt++) {
            #pragma unroll
            for (int c = 0; c < 2; c++) {
                int j = n0 + nt * 8 + tig * 2 + c;
                if (j < NTOK) {
                    int jr = j / 7, jc = j % 7;
                    if (r0 < NTOK)
                        SCR[r0 * AST + j] = d[nt][c] * SCALEF
                            + RPB[((i0r - jr + 6) * 13 + (i0c - jc + 6)) * 3 + h];
                    if (r1 < NTOK)
                        SCR[r1 * AST + j] = d[nt][2 + c] * SCALEF
                            + RPB[((i1r - jr + 6) * 13 + (i1c - jc + 6)) * 3 + h];
                }
            }
        }
    }
}

// ---- attn@V (ALL heads): 24 slots over 12 warps ----------------------------
__device__ __forceinline__ void attnv_mma(const float* SC, const float* V,
                                          float* O, int warp, int lane)
{
    const int gid = lane >> 2, tig = lane & 3;
    for (int slot = warp; slot < 24; slot += 12) {
        const int h = slot >> 3, q = slot & 7;
        const int m0 = (q >> 1) * 16, n0 = (q & 1) * 16;
        const int ch0 = h * HDIM;
        const float* SCR = SC + h * SCRH;
        float d[2][4];
        #pragma unroll
        for (int i = 0; i < 2; i++) { d[i][0] = d[i][1] = d[i][2] = d[i][3] = 0.f; }
        const float* Pr0 = SCR + (m0 + gid) * AST;
        const float* Pr1 = Pr0 + 8 * AST;
        #pragma unroll
        for (int kc = 0; kc < 4; kc++) {
            const int k0 = 2 * (kc * 8 + tig);
            const int k2 = k0 + 8;
            uint32_t a0h = 0, a0l = 0, a1h = 0, a1l = 0;
            uint32_t a2h = 0, a2l = 0, a3h = 0, a3l = 0;
            if (k0 <= 48) {
                split2(*reinterpret_cast<const float2*>(Pr0 + k0), a0h, a0l);
                split2(*reinterpret_cast<const float2*>(Pr1 + k0), a1h, a1l);
            }
            if (k2 <= 48) {
                split2(*reinterpret_cast<const float2*>(Pr0 + k2), a2h, a2l);
                split2(*reinterpret_cast<const float2*>(Pr1 + k2), a3h, a3l);
            }
            #pragma unroll
            for (int nt = 0; nt < 2; nt++) {
                const int n = ch0 + n0 + nt * 8 + gid;
                uint32_t b0h, b0l, b1h, b1l;
                split2(make_float2(V[k0 * ST + n], V[(k0 + 1) * ST + n]), b0h, b0l);
                split2(make_float2(V[k2 * ST + n], V[(k2 + 1) * ST + n]), b1h, b1l);
                mma16(d[nt], a0h, a1h, a2h, a3h, b0h, b1h);
                mma16(d[nt], a0h, a1h, a2h, a3h, b0l, b1l);
                mma16(d[nt], a0l, a1l, a2l, a3l, b0h, b1h);
            }
        }
        const int r0 = m0 + gid, r1 = r0 + 8;
        #pragma unroll
        for (int nt = 0; nt < 2; nt++) {
            int n = ch0 + n0 + nt * 8 + tig * 2;
            if (r0 < NTOK)
                *reinterpret_cast<float2*>(O + r0 * ST + n) = make_float2(d[nt][0], d[nt][1]);
            if (r1 < NTOK)
                *reinterpret_cast<float2*>(O + r1 * ST + n) = make_float2(d[nt][2], d[nt][3]);
        }
    }
}

// ---- cattn via MMA: 12 slots = 3h x 2m x 2e-half ---------------------------
__device__ __forceinline__ void cattn_mma(const float* QS, const float* KS,
                                          float* CAT, const float* NQ, const float* NK,
                                          int warp, int lane)
{
    const int h = warp >> 2, mt = (warp >> 1) & 1, eh = warp & 1;
    const int ch = h * HDIM, m0 = mt * 16, e0b = eh * 16;
    const int gid = lane >> 2, tig = lane & 3;
    float d[2][4];
    #pragma unroll
    for (int i = 0; i < 2; i++) { d[i][0] = d[i][1] = d[i][2] = d[i][3] = 0.f; }
    #pragma unroll
    for (int kc = 0; kc < 4; kc++) {
        const int k0 = 2 * (kc * 8 + tig);
        const int k1 = k0 + 1, k2 = k0 + 8, k3 = k0 + 9;
        const int ca = ch + m0 + gid;
        float a00 = (k0 < NTOK) ? KS[k0 * ST + ca] : 0.f;
        float a01 = (k1 < NTOK) ? KS[k1 * ST + ca] : 0.f;
        float a10 = (k0 < NTOK) ? KS[k0 * ST + ca + 8] : 0.f;
        float a11 = (k1 < NTOK) ? KS[k1 * ST + ca + 8] : 0.f;
        float a20 = (k2 < NTOK) ? KS[k2 * ST + ca] : 0.f;
        float a21 = (k3 < NTOK) ? KS[k3 * ST + ca] : 0.f;
        float a30 = (k2 < NTOK) ? KS[k2 * ST + ca + 8] : 0.f;
        float a31 = (k3 < NTOK) ? KS[k3 * ST + ca + 8] : 0.f;
        uint32_t a0h, a0l, a1h, a1l, a2h, a2l, a3h, a3l;
        split2(make_float2(a00, a01), a0h, a0l);
        split2(make_float2(a10, a11), a1h, a1l);
        split2(make_float2(a20, a21), a2h, a2l);
        split2(make_float2(a30, a31), a3h, a3l);
        #pragma unroll
        for (int nt = 0; nt < 2; nt++) {
            const int ce = ch + e0b + nt * 8 + gid;
            float b00 = (k0 < NTOK) ? QS[k0 * ST + ce] : 0.f;
            float b01 = (k1 < NTOK) ? QS[k1 * ST + ce] : 0.f;
            float b10 = (k2 < NTOK) ? QS[k2 * ST + ce] : 0.f;
            float b11 = (k3 < NTOK) ? QS[k3 * ST + ce] : 0.f;
            uint32_t b0h, b0l, b1h, b1l;
            split2(make_float2(b00, b01), b0h, b0l);
            split2(make_float2(b10, b11), b1h, b1l);
            mma16(d[nt], a0h, a1h, a2h, a3h, b0h, b1h);
            mma16(d[nt], a0h, a1h, a2h, a3h, b0l, b1l);
            mma16(d[nt], a0l, a1l, a2l, a3l, b0h, b1h);
        }
    }
    const int r0 = m0 + gid, r1 = r0 + 8;
    const float sk0 = NK[ch + r0] * SCALEF;
    const float sk1 = NK[ch + r1] * SCALEF;
    float* C0 = CAT + h * 1088 + r0 * CST;
    float* C1 = CAT + h * 1088 + r1 * CST;
    #pragma unroll
    for (int nt = 0; nt < 2; nt++) {
        int e0 = e0b + nt * 8 + tig * 2;
        float q0 = NQ[ch + e0], q1 = NQ[ch + e0 + 1];
        C0[e0]     = d[nt][0] * sk0 * q0;
        C0[e0 + 1] = d[nt][1] * sk0 * q1;
        C1[e0]     = d[nt][2] * sk1 * q0;
        C1[e0 + 1] = d[nt][3] * sk1 * q1;
    }
}

// ---- xc via MMA: 12 slots = 3h x 4 m-tiles ---------------------------------
__device__ __forceinline__ void xc_mma(const float* CAT, const float* V, float* O,
                                       int warp, int lane)
{
    const int h = warp >> 2, mt = warp & 3;
    const int ch = h * HDIM, m0 = mt * 16;
    const int gid = lane >> 2, tig = lane & 3;
    float d[4][4];
    #pragma unroll
    for (int i = 0; i < 4; i++) { d[i][0] = d[i][1] = d[i][2] = d[i][3] = 0.f; }
    const float* Ar0 = V + (m0 + gid) * ST + ch;
    const float* Ar1 = Ar0 + 8 * ST;
    #pragma unroll
    for (int kc = 0; kc < 2; kc++) {
        const int kp = kc * 8 + tig;
        uint32_t a0h, a0l, a1h, a1l, a2h, a2l, a3h, a3l;
        split2(*reinterpret_cast<const float2*>(Ar0 + 2 * kp), a0h, a0l);
        split2(*reinterpret_cast<const float2*>(Ar1 + 2 * kp), a1h, a1l);
        split2(*reinterpret_cast<const float2*>(Ar0 + 2 * kp + 8), a2h, a2l);
        split2(*reinterpret_cast<const float2*>(Ar1 + 2 * kp + 8), a3h, a3l);
        #pragma unroll
        for (int nt = 0; nt < 4; nt++) {
            const float* Br = CAT + h * 1088 + (nt * 8 + gid) * CST;
            uint32_t b0h, b0l, b1h, b1l;
            split2(*reinterpret_cast<const float2*>(Br + 2 * kp), b0h, b0l);
            split2(*reinterpret_cast<const float2*>(Br + 2 * kp + 8), b1h, b1l);
            mma16(d[nt], a0h, a1h, a2h, a3h, b0h, b1h);
            mma16(d[nt], a0h, a1h, a2h, a3h, b0l, b1l);
            mma16(d[nt], a0l, a1l, a2l, a3l, b0h, b1h);
        }
    }
    const int r0 = m0 + gid, r1 = r0 + 8;
    #pragma unroll
    for (int nt = 0; nt < 4; nt++) {
        int n = ch + nt * 8 + tig * 2;
        if (r0 < NTOK)
            *reinterpret_cast<float2*>(O + r0 * ST + n) = make_float2(d[nt][0], d[nt][1]);
        if (r1 < NTOK)
            *reinterpret_cast<float2*>(O + r1 * ST + n) = make_float2(d[nt][2], d[nt][3]);
    }
}

// ---- depthwise 3x3 conv: 24 ch-grp x 16 tok-grp (384 threads) --------------
__device__ __forceinline__ void dwconv4(const float* In, const float* __restrict__ Wc,
                                        float* Out, int tid, int mode)
{
    const int c0 = (tid >> 4) * 4, t0 = (tid & 15) * 4;
    u64 wc[9][2];
    #pragma unroll
    for (int s = 0; s < 9; s++) {
        const ulonglong2* wp = reinterpret_cast<const ulonglong2*>(Wc + s * 96 + c0);
        ulonglong2 w = *wp;
        wc[s][0] = w.x; wc[s][1] = w.y;
    }
    #pragma unroll
    for (int tt = 0; tt < 4; tt++) {
        int t = t0 + tt;
        if (t >= NTOK) break;
        int r = t / 7, cc = t % 7;
        u64 a0 = 0ULL, a1 = 0ULL;
        #pragma unroll
        for (int dr = 0; dr < 3; dr++) {
            int rr = r + dr - 1;
            if (rr < 0 || rr > 6) continue;
            #pragma unroll
            for (int dc = 0; dc < 3; dc++) {
                int c2 = cc + dc - 1;
                if (c2 < 0 || c2 > 6) continue;
                const float* vp = In + (rr * 7 + c2) * ST + c0;
                fma2(a0, lds64(vp), wc[dr * 3 + dc][0]);
                fma2(a1, lds64(vp + 2), wc[dr * 3 + dc][1]);
            }
        }
        float2 p0 = unp(a0), p1 = unp(a1);
        float* o = Out + t * ST + c0;
        if (mode == 0) {
            o[0] = 0.5f * p0.x * (1.f + erff(p0.x * 0.70710678118654752f));
            o[1] = 0.5f * p0.y * (1.f + erff(p0.y * 0.70710678118654752f));
            o[2] = 0.5f * p1.x * (1.f + erff(p1.x * 0.70710678118654752f));
            o[3] = 0.5f * p1.y * (1.f + erff(p1.y * 0.70710678118654752f));
        } else {
            o[0] += p0.x; o[1] += p0.y; o[2] += p1.x; o[3] += p1.y;
        }
    }
}

__global__ __launch_bounds__(NTHR, 2) void winattn_kernel(
    const float* __restrict__ x,
    const float* __restrict__ rpb_table,
    const float* __restrict__ bq,  const float* __restrict__ bk,
    const float* __restrict__ bv,  const float* __restrict__ b_ps,
    const float* __restrict__ b_pc,
    const float* __restrict__ conv1, const float* __restrict__ conv2,
    const float* __restrict__ b_proj,
    float* __restrict__ out)
{
    extern __shared__ float sm[];
    float* A   = sm + OFF_A;      // x -> xc
    float* Bb  = sm + OFF_B;      // q -> sp -> ks -> conv1out
    float* Cc  = sm + OFF_C;      // k -> spat
    float* Dd  = sm + OFF_D;      // v
    float* Ee  = sm + OFF_E;      // scores(+CAT spill) -> qs -> out_c/spec
    float* RPB = sm + OFF_RPB;
    float* NQ  = sm + OFF_NQ;
    float* NK  = sm + OFF_NK;
    float* CAT = sm + OFF_CAT;

    const int tid  = threadIdx.x;
    const int blk  = blockIdx.x;
    const int warp = tid >> 5, lane = tid & 31;

    {
        const float4* xg4 = reinterpret_cast<const float4*>(x + (size_t)blk * (NTOK * NCH));
        for (int i4 = tid; i4 < NTOK * 24; i4 += NTHR) {
            float4 v = xg4[i4];
            int t = i4 / 24, c = (i4 % 24) * 4;
            float* p = A + t * ST + c;
            p[0] = v.x; p[1] = v.y; p[2] = v.z; p[3] = v.w;
        }
        for (int i = tid; i < 507; i += NTHR) RPB[i] = rpb_table[i];
    }
    __syncthreads();

    // ---- q, k, v projections (independent: one barrier) ----
    gemm_bf16(A, 0 * FRAG_PER_G, bq, Bb, warp, lane);
    gemm_bf16(A, 1 * FRAG_PER_G, bk, Cc, warp, lane);
    gemm_bf16(A, 2 * FRAG_PER_G, bv, Dd, warp, lane);
    __syncthreads();

    // ---- attention: one scores phase, one softmax, one attn@V ----
    scores_mma(Bb, Cc, Ee, RPB, warp, lane);
    __syncthreads();
    for (int r = warp; r < 3 * NTOK; r += 12) {
        float* row = Ee + (r / NTOK) * SCRH + (r % NTOK) * AST;
        float e1 = row[lane];
        bool hi = (lane + 32) < NTOK;
        float e2 = hi ? row[lane + 32] : -3.4e38f;
        float m = fmaxf(e1, e2);
        #pragma unroll
        for (int o = 16; o > 0; o >>= 1) m = fmaxf(m, __shfl_xor_sync(0xffffffffu, m, o));
        float p1 = __expf(e1 - m);
        float p2 = hi ? __expf(e2 - m) : 0.f;
        float s = p1 + p2;
        #pragma unroll
        for (int o = 16; o > 0; o >>= 1) s += __shfl_xor_sync(0xffffffffu, s, o);
        float inv = 1.f / s;
        row[lane] = p1 * inv;
        if (hi) row[lane + 32] = p2 * inv;
        if (lane == 0) row[NTOK] = 0.f;
    }
    __syncthreads();
    attnv_mma(Ee, Dd, Bb, warp, lane);
    __syncthreads();

    // ---- {spatial = sp @ w_ps -> C} and {qs = x @ wq_sp -> E} ----
    gemm_bf16(Bb, 3 * FRAG_PER_G, b_ps, Cc, warp, lane);
    gemm_bf16(A, 4 * FRAG_PER_G, 0, Ee, warp, lane);
    __syncthreads();
    // ---- ks = x @ wk_sp -> B ----
    gemm_bf16(A, 5 * FRAG_PER_G, 0, Bb, warp, lane);
    __syncthreads();

    // ---- inverse L2 norms per channel ----
    if (tid < 96) {
        float s = 0.f;
        for (int t = 0; t < NTOK; t++) { float v = Ee[t * ST + tid]; s += v * v; }
        NQ[tid] = rsqrtf(fmaxf(s, 1e-24f));
    } else if (tid < 192) {
        int c = tid - 96;
        float s = 0.f;
        for (int t = 0; t < NTOK; t++) { float v = Bb[t * ST + c]; s += v * v; }
        NK[c] = rsqrtf(fmaxf(s, 1e-24f));
    }
    __syncthreads();

    // ---- cattn raw + normalize (MMA) ----
    cattn_mma(Ee, Bb, CAT, NQ, NK, warp, lane);
    __syncthreads();
    // ---- cattn softmax: 96 rows over 12 warps ----
    for (int rid = warp; rid < 96; rid += 12) {
        float* row = CAT + (rid >> 5) * 1088 + (rid & 31) * CST;
        float e = row[lane];
        float m = e;
        #pragma unroll
        for (int o = 16; o > 0; o >>= 1) m = fmaxf(m, __shfl_xor_sync(0xffffffffu, m, o));
        float p = __expf(e - m);
        float s = p;
        #pragma unroll
        for (int o = 16; o > 0; o >>= 1) s += __shfl_xor_sync(0xffffffffu, s, o);
        row[lane] = p * (1.f / s);
    }
    __syncthreads();

    // ---- xc = cattn @ v -> A (MMA) ----
    xc_mma(CAT, Dd, A, warp, lane);
    __syncthreads();

    // ---- {out_c = xc @ w_pc -> E} then {conv1(v)+GELU -> B} ----
    gemm_bf16(A, 6 * FRAG_PER_G, b_pc, Ee, warp, lane);
    dwconv4(Dd, conv1, Bb, tid, 0);
    __syncthreads();

    // ---- conv2(gelu) -> E += ----
    dwconv4(Bb, conv2, Ee, tid, 1);
    __syncthreads();

    // ---- final projection ----
    proj_bf16(Cc, Ee, b_proj, out + (size_t)blk * (NTOK * NCH), warp, lane);
}

extern "C" void kernel_launch(void* const* d_in, const int* in_sizes, int n_in,
                              void* d_out, int out_size)
{
    const float* x      = (const float*)d_in[0];
    const float* rpb    = (const float*)d_in[1];
    const float* wq     = (const float*)d_in[2];
    const float* bq     = (const float*)d_in[3];
    const float* wk     = (const float*)d_in[4];
    const float* bk     = (const float*)d_in[5];
    const float* wv     = (const float*)d_in[6];
    const float* bv     = (const float*)d_in[7];
    const float* w_ps   = (const float*)d_in[8];
    const float* b_ps   = (const float*)d_in[9];
    const float* wq_sp  = (const float*)d_in[10];
    const float* wk_sp  = (const float*)d_in[11];
    const float* w_pc   = (const float*)d_in[12];
    const float* b_pc   = (const float*)d_in[13];
    const float* conv1  = (const float*)d_in[14];
    const float* conv2  = (const float*)d_in[15];
    const float* w_proj = (const float*)d_in[16];
    const float* b_proj = (const float*)d_in[17];
    float* out = (float*)d_out;

    int nwin = in_sizes[0] / (NTOK * NCH);

    prep_weights<<<(NFRAG + 255) / 256, 256>>>(wq, wk, wv, w_ps, wq_sp, wk_sp, w_pc, w_proj);

    cudaFuncSetAttribute(winattn_kernel,
                         cudaFuncAttributeMaxDynamicSharedMemorySize, SMEM_BYTES);
    winattn_kernel<<<nwin, NTHR, SMEM_BYTES>>>(
        x, rpb, bq, bk, bv, b_ps, b_pc, conv1, conv2, b_proj, out);
}

// round 12
// speedup vs baseline: 1.0835x; 1.0835x over previous
#include <cuda_runtime.h>
#include <math.h>
#include <stdint.h>

// ---------------------------------------------------------------------------
// WindowAttention fused kernel, round 12 (base R10, 256 thr):
//  - gemm2: M=32 per warp -> each B-fragment LDG feeds 6 MMAs (B traffic /2)
//  - v-projection overlapped with attention scores (different warp halves)
//  - merged all-head softmax/attnv phases
// ---------------------------------------------------------------------------

#define NTOK   49
#define NCH    96
#define NHEADS 3
#define HDIM   32
#define ST     100
#define AST    50
#define CST    34
#define SCALEF 0.17677669529663687f
#define NTHR   256

#define BUF     (NTOK*ST)                  // 4900
#define OFF_A   0
#define OFF_B   (OFF_A + BUF)
#define OFF_C   (OFF_B + BUF)
#define OFF_D   (OFF_C + BUF)
#define OFF_RPB (OFF_D + BUF)              // 508
#define OFF_NQ  (OFF_RPB + 508)            // 96
#define OFF_NK  (OFF_NQ + 96)              // 96
#define OFF_E   (OFF_NK + 96)              // 4900 (scores span E+CAT: 8164)
#define OFF_CAT (OFF_E + BUF)              // 3264
#define SMEM_FLOATS (OFF_CAT + 3264)
#define SMEM_BYTES  (SMEM_FLOATS * 4)      // 113856

#define SCRH    2450                       // per-head score block (49*50)

#define FRAG_PER_G 2304
#define PROJ_FBASE (7 * FRAG_PER_G)
#define NFRAG      (PROJ_FBASE + 12 * 12 * 32)

__device__ uint4 g_wpack[NFRAG];

typedef unsigned long long u64;

__device__ __forceinline__ void fma2(u64& d, u64 a, u64 b) {
    asm("fma.rn.f32x2 %0,%1,%2,%0;" : "+l"(d) : "l"(a), "l"(b));
}
__device__ __forceinline__ float2 unp(u64 a) {
    float2 r; asm("mov.b64 {%0,%1},%2;" : "=f"(r.x), "=f"(r.y) : "l"(a)); return r;
}
__device__ __forceinline__ u64 lds64(const float* p) {
    return *reinterpret_cast<const u64*>(p);
}
__device__ __forceinline__ uint32_t cvtbf2(float h, float l) {
    uint32_t r; asm("cvt.rn.bf16x2.f32 %0, %1, %2;" : "=r"(r) : "f"(h), "f"(l)); return r;
}
__device__ __forceinline__ float blo2f(uint32_t p) { return __uint_as_float(p << 16); }
__device__ __forceinline__ float bhi2f(uint32_t p) { return __uint_as_float(p & 0xFFFF0000u); }

__device__ __forceinline__ void mma16(float d[4],
                                      uint32_t a0, uint32_t a1, uint32_t a2, uint32_t a3,
                                      uint32_t b0, uint32_t b1) {
    asm volatile("mma.sync.aligned.m16n8k16.row.col.f32.bf16.bf16.f32 "
                 "{%0,%1,%2,%3}, {%4,%5,%6,%7}, {%8,%9}, {%0,%1,%2,%3};"
                 : "+f"(d[0]), "+f"(d[1]), "+f"(d[2]), "+f"(d[3])
                 : "r"(a0), "r"(a1), "r"(a2), "r"(a3), "r"(b0), "r"(b1));
}

__device__ __forceinline__ void split2(float2 p, uint32_t& h, uint32_t& l) {
    h = cvtbf2(p.y, p.x);
    l = cvtbf2(p.y - bhi2f(h), p.x - blo2f(h));
}

// ---------------- prologue: pack weight B-fragments in warp order -----------
__global__ void prep_weights(const float* __restrict__ wq, const float* __restrict__ wk,
                             const float* __restrict__ wv, const float* __restrict__ w_ps,
                             const float* __restrict__ wq_sp, const float* __restrict__ wk_sp,
                             const float* __restrict__ w_pc, const float* __restrict__ w_proj)
{
    int idx = blockIdx.x * 256 + threadIdx.x;
    if (idx >= NFRAG) return;
    const float* Wt[8] = {wq, wk, wv, w_ps, wq_sp, wk_sp, w_pc, w_proj};
    int g, r;
    if (idx < PROJ_FBASE) { g = idx / FRAG_PER_G; r = idx % FRAG_PER_G; }
    else                  { g = 7; r = idx - PROJ_FBASE; }
    int kc   = r / 384;
    int rem  = r % 384;
    int slot = rem / 32;
    int lane = rem % 32;
    int gid = lane >> 2, tig = lane & 3;
    int kp = kc * 8 + tig;
    int n  = slot * 8 + gid;
    const float* W = Wt[g];
    float x0 = W[(2 * kp) * 96 + n];
    float x1 = W[(2 * kp + 1) * 96 + n];
    float y0 = W[(2 * kp + 8) * 96 + n];
    float y1 = W[(2 * kp + 9) * 96 + n];
    uint32_t b0h, b0l, b1h, b1l;
    split2(make_float2(x0, x1), b0h, b0l);
    split2(make_float2(y0, y1), b1h, b1l);
    g_wpack[idx] = make_uint4(b0h, b1h, b0l, b1l);
}

// ---- gemm2: M=32 x N=48 per warp-slot (sub in [0,4)), B-frag reuse x2 ------
__device__ __forceinline__ void gemm2_bf16(const float* Xs, int fbase,
                                           const float* __restrict__ bias, float* Os,
                                           int sub, int lane)
{
    const int m0 = (sub >> 1) * 32;
    const int nh = sub & 1, n0 = nh * 48;
    const int gid = lane >> 2, tig = lane & 3;
    float d[2][6][4];
    #pragma unroll
    for (int m = 0; m < 2; m++)
        #pragma unroll
        for (int i = 0; i < 6; i++) { d[m][i][0] = d[m][i][1] = d[m][i][2] = d[m][i][3] = 0.f; }
    const float* X0 = Xs + (m0 + gid) * ST;
    const float* X1 = Xs + (m0 + gid + 8) * ST;
    const float* X2 = Xs + (m0 + gid + 16) * ST;
    const float* X3 = Xs + (m0 + gid + 24) * ST;
    #pragma unroll
    for (int kc = 0; kc < 6; kc++) {
        const int kp = kc * 8 + tig;
        uint32_t ah[2][4], al[2][4];
        split2(*reinterpret_cast<const float2*>(X0 + 2 * kp),     ah[0][0], al[0][0]);
        split2(*reinterpret_cast<const float2*>(X1 + 2 * kp),     ah[0][1], al[0][1]);
        split2(*reinterpret_cast<const float2*>(X0 + 2 * kp + 8), ah[0][2], al[0][2]);
        split2(*reinterpret_cast<const float2*>(X1 + 2 * kp + 8), ah[0][3], al[0][3]);
        split2(*reinterpret_cast<const float2*>(X2 + 2 * kp),     ah[1][0], al[1][0]);
        split2(*reinterpret_cast<const float2*>(X3 + 2 * kp),     ah[1][1], al[1][1]);
        split2(*reinterpret_cast<const float2*>(X2 + 2 * kp + 8), ah[1][2], al[1][2]);
        split2(*reinterpret_cast<const float2*>(X3 + 2 * kp + 8), ah[1][3], al[1][3]);
        const uint4* Bf = g_wpack + fbase + (kc * 12 + nh * 6) * 32 + lane;
        #pragma unroll
        for (int nt = 0; nt < 6; nt++) {
            uint4 w = Bf[nt * 32];
            #pragma unroll
            for (int m = 0; m < 2; m++) {
                mma16(d[m][nt], ah[m][0], ah[m][1], ah[m][2], ah[m][3], w.x, w.y);
                mma16(d[m][nt], ah[m][0], ah[m][1], ah[m][2], ah[m][3], w.z, w.w);
                mma16(d[m][nt], al[m][0], al[m][1], al[m][2], al[m][3], w.x, w.y);
            }
        }
    }
    #pragma unroll
    for (int m = 0; m < 2; m++) {
        const int r0 = m0 + m * 16 + gid, r1 = r0 + 8;
        #pragma unroll
        for (int nt = 0; nt < 6; nt++) {
            int n = n0 + nt * 8 + tig * 2;
            float bx = 0.f, by = 0.f;
            if (bias) { bx = bias[n]; by = bias[n + 1]; }
            if (r0 < NTOK) { float* o = Os + r0 * ST + n; o[0] = d[m][nt][0] + bx; o[1] = d[m][nt][1] + by; }
            if (r1 < NTOK) { float* o = Os + r1 * ST + n; o[0] = d[m][nt][2] + bx; o[1] = d[m][nt][3] + by; }
        }
    }
}

// ---- R10-style 8-warp GEMM (for solo phases: ks, out_c) --------------------
__device__ __forceinline__ void gemm_bf16(const float* Xs, int fbase,
                                          const float* __restrict__ bias, float* Os,
                                          int warp, int lane)
{
    const int m0 = (warp >> 1) * 16;
    const int nh = warp & 1;
    const int n0 = nh * 48;
    const int gid = lane >> 2, tig = lane & 3;
    float d[6][4];
    #pragma unroll
    for (int i = 0; i < 6; i++) { d[i][0] = d[i][1] = d[i][2] = d[i][3] = 0.f; }
    const float* Xr0 = Xs + (m0 + gid) * ST;
    const float* Xr1 = Xs + (m0 + gid + 8) * ST;
    #pragma unroll
    for (int kc = 0; kc < 6; kc++) {
        const int kp = kc * 8 + tig;
        uint32_t a0h, a0l, a1h, a1l, a2h, a2l, a3h, a3l;
        split2(*reinterpret_cast<const float2*>(Xr0 + 2 * kp), a0h, a0l);
        split2(*reinterpret_cast<const float2*>(Xr1 + 2 * kp), a1h, a1l);
        split2(*reinterpret_cast<const float2*>(Xr0 + 2 * kp + 8), a2h, a2l);
        split2(*reinterpret_cast<const float2*>(Xr1 + 2 * kp + 8), a3h, a3l);
        const uint4* Bf = g_wpack + fbase + (kc * 12 + nh * 6) * 32 + lane;
        #pragma unroll
        for (int nt = 0; nt < 6; nt++) {
            uint4 w = Bf[nt * 32];
            mma16(d[nt], a0h, a1h, a2h, a3h, w.x, w.y);
            mma16(d[nt], a0h, a1h, a2h, a3h, w.z, w.w);
            mma16(d[nt], a0l, a1l, a2l, a3l, w.x, w.y);
        }
    }
    const int r0 = m0 + gid, r1 = m0 + gid + 8;
    #pragma unroll
    for (int nt = 0; nt < 6; nt++) {
        int n = n0 + nt * 8 + tig * 2;
        float bx = 0.f, by = 0.f;
        if (bias) { bx = bias[n]; by = bias[n + 1]; }
        if (r0 < NTOK) { float* o = Os + r0 * ST + n; o[0] = d[nt][0] + bx; o[1] = d[nt][1] + by; }
        if (r1 < NTOK) { float* o = Os + r1 * ST + n; o[0] = d[nt][2] + bx; o[1] = d[nt][3] + by; }
    }
}

// ---- final projection with B-frag reuse: M=32 x N=48, K=192, sub in [0,4) --
__device__ __forceinline__ void proj2_bf16(const float* Sa, const float* Sb,
                                           const float* __restrict__ bias,
                                           float* __restrict__ og, int sub, int lane)
{
    const int m0 = (sub >> 1) * 32;
    const int nh = sub & 1, n0 = nh * 48;
    const int gid = lane >> 2, tig = lane & 3;
    float d[2][6][4];
    #pragma unroll
    for (int m = 0; m < 2; m++)
        #pragma unroll
        for (int i = 0; i < 6; i++) { d[m][i][0] = d[m][i][1] = d[m][i][2] = d[m][i][3] = 0.f; }
    #pragma unroll
    for (int kc = 0; kc < 12; kc++) {
        const int kp = (kc % 6) * 8 + tig;
        const float* Xb = (kc < 6) ? Sa : Sb;
        const float* X0 = Xb + (m0 + gid) * ST;
        const float* X1 = X0 + 8 * ST;
        const float* X2 = X0 + 16 * ST;
        const float* X3 = X0 + 24 * ST;
        uint32_t ah[2][4], al[2][4];
        split2(*reinterpret_cast<const float2*>(X0 + 2 * kp),     ah[0][0], al[0][0]);
        split2(*reinterpret_cast<const float2*>(X1 + 2 * kp),     ah[0][1], al[0][1]);
        split2(*reinterpret_cast<const float2*>(X0 + 2 * kp + 8), ah[0][2], al[0][2]);
        split2(*reinterpret_cast<const float2*>(X1 + 2 * kp + 8), ah[0][3], al[0][3]);
        split2(*reinterpret_cast<const float2*>(X2 + 2 * kp),     ah[1][0], al[1][0]);
        split2(*reinterpret_cast<const float2*>(X3 + 2 * kp),     ah[1][1], al[1][1]);
        split2(*reinterpret_cast<const float2*>(X2 + 2 * kp + 8), ah[1][2], al[1][2]);
        split2(*reinterpret_cast<const float2*>(X3 + 2 * kp + 8), ah[1][3], al[1][3]);
        const uint4* Bf = g_wpack + PROJ_FBASE + (kc * 12 + nh * 6) * 32 + lane;
        #pragma unroll
        for (int nt = 0; nt < 6; nt++) {
            uint4 w = Bf[nt * 32];
            #pragma unroll
            for (int m = 0; m < 2; m++) {
                mma16(d[m][nt], ah[m][0], ah[m][1], ah[m][2], ah[m][3], w.x, w.y);
                mma16(d[m][nt], ah[m][0], ah[m][1], ah[m][2], ah[m][3], w.z, w.w);
                mma16(d[m][nt], al[m][0], al[m][1], al[m][2], al[m][3], w.x, w.y);
            }
        }
    }
    #pragma unroll
    for (int m = 0; m < 2; m++) {
        const int r0 = m0 + m * 16 + gid, r1 = r0 + 8;
        #pragma unroll
        for (int nt = 0; nt < 6; nt++) {
            int n = n0 + nt * 8 + tig * 2;
            float bx = bias[n], by = bias[n + 1];
            if (r0 < NTOK) {
                float2 v = make_float2(d[m][nt][0] + bx, d[m][nt][1] + by);
                *reinterpret_cast<float2*>(og + r0 * NCH + n) = v;
            }
            if (r1 < NTOK) {
                float2 v = make_float2(d[m][nt][2] + bx, d[m][nt][3] + by);
                *reinterpret_cast<float2*>(og + r1 * NCH + n) = v;
            }
        }
    }
}

// ---- scores (ALL heads): 24 slots, strided over the calling warps ----------
__device__ __forceinline__ void scores_mma(const float* Q, const float* K,
                                           float* SC, const float* RPB,
                                           int slot0, int stride, int lane)
{
    const int gid = lane >> 2, tig = lane & 3;
    for (int slot = slot0; slot < 24; slot += stride) {
        const int h = slot >> 3, q = slot & 7;
        const int m0 = (q >> 1) * 16, n0 = (q & 1) * 32;
        const int ch0 = h * HDIM;
        float* SCR = SC + h * SCRH;
        float d[4][4];
        #pragma unroll
        for (int i = 0; i < 4; i++) { d[i][0] = d[i][1] = d[i][2] = d[i][3] = 0.f; }
        const float* Qr0 = Q + (m0 + gid) * ST + ch0;
        const float* Qr1 = Qr0 + 8 * ST;
        #pragma unroll
        for (int kc = 0; kc < 2; kc++) {
            const int kp = kc * 8 + tig;
            uint32_t a0h, a0l, a1h, a1l, a2h, a2l, a3h, a3l;
            split2(*reinterpret_cast<const float2*>(Qr0 + 2 * kp), a0h, a0l);
            split2(*reinterpret_cast<const float2*>(Qr1 + 2 * kp), a1h, a1l);
            split2(*reinterpret_cast<const float2*>(Qr0 + 2 * kp + 8), a2h, a2l);
            split2(*reinterpret_cast<const float2*>(Qr1 + 2 * kp + 8), a3h, a3l);
            #pragma unroll
            for (int nt = 0; nt < 4; nt++) {
                const float* Kr = K + (n0 + nt * 8 + gid) * ST + ch0;
                uint32_t b0h, b0l, b1h, b1l;
                split2(*reinterpret_cast<const float2*>(Kr + 2 * kp), b0h, b0l);
                split2(*reinterpret_cast<const float2*>(Kr + 2 * kp + 8), b1h, b1l);
                mma16(d[nt], a0h, a1h, a2h, a3h, b0h, b1h);
                mma16(d[nt], a0h, a1h, a2h, a3h, b0l, b1l);
                mma16(d[nt], a0l, a1l, a2l, a3l, b0h, b1h);
            }
        }
        const int r0 = m0 + gid, r1 = r0 + 8;
        const int i0r = r0 / 7, i0c = r0 % 7;
        const int i1r = r1 / 7, i1c = r1 % 7;
        #pragma unroll
        for (int nt = 0; nt < 4; nt++) {
            #pragma unroll
            for (int c = 0; c < 2; c++) {
                int j = n0 + nt * 8 + tig * 2 + c;
                if (j < NTOK) {
                    int jr = j / 7, jc = j % 7;
                    if (r0 < NTOK)
                        SCR[r0 * AST + j] = d[nt][c] * SCALEF
                            + RPB[((i0r - jr + 6) * 13 + (i0c - jc + 6)) * 3 + h];
                    if (r1 < NTOK)
                        SCR[r1 * AST + j] = d[nt][2 + c] * SCALEF
                            + RPB[((i1r - jr + 6) * 13 + (i1c - jc + 6)) * 3 + h];
                }
            }
        }
    }
}

// ---- attn@V (ALL heads): 24 slots over 8 warps ------------------------------
__device__ __forceinline__ void attnv_mma(const float* SC, const float* V,
                                          float* O, int warp, int lane)
{
    const int gid = lane >> 2, tig = lane & 3;
    for (int slot = warp; slot < 24; slot += 8) {
        const int h = slot >> 3, q = slot & 7;
        const int m0 = (q >> 1) * 16, n0 = (q & 1) * 16;
        const int ch0 = h * HDIM;
        const float* SCR = SC + h * SCRH;
        float d[2][4];
        #pragma unroll
        for (int i = 0; i < 2; i++) { d[i][0] = d[i][1] = d[i][2] = d[i][3] = 0.f; }
        const float* Pr0 = SCR + (m0 + gid) * AST;
        const float* Pr1 = Pr0 + 8 * AST;
        #pragma unroll
        for (int kc = 0; kc < 4; kc++) {
            const int k0 = 2 * (kc * 8 + tig);
            const int k2 = k0 + 8;
            uint32_t a0h = 0, a0l = 0, a1h = 0, a1l = 0;
            uint32_t a2h = 0, a2l = 0, a3h = 0, a3l = 0;
            if (k0 <= 48) {
                split2(*reinterpret_cast<const float2*>(Pr0 + k0), a0h, a0l);
                split2(*reinterpret_cast<const float2*>(Pr1 + k0), a1h, a1l);
            }
            if (k2 <= 48) {
                split2(*reinterpret_cast<const float2*>(Pr0 + k2), a2h, a2l);
                split2(*reinterpret_cast<const float2*>(Pr1 + k2), a3h, a3l);
            }
            #pragma unroll
            for (int nt = 0; nt < 2; nt++) {
                const int n = ch0 + n0 + nt * 8 + gid;
                uint32_t b0h, b0l, b1h, b1l;
                split2(make_float2(V[k0 * ST + n], V[(k0 + 1) * ST + n]), b0h, b0l);
                split2(make_float2(V[k2 * ST + n], V[(k2 + 1) * ST + n]), b1h, b1l);
                mma16(d[nt], a0h, a1h, a2h, a3h, b0h, b1h);
                mma16(d[nt], a0h, a1h, a2h, a3h, b0l, b1l);
                mma16(d[nt], a0l, a1l, a2l, a3l, b0h, b1h);
            }
        }
        const int r0 = m0 + gid, r1 = r0 + 8;
        #pragma unroll
        for (int nt = 0; nt < 2; nt++) {
            int n = ch0 + n0 + nt * 8 + tig * 2;
            if (r0 < NTOK)
                *reinterpret_cast<float2*>(O + r0 * ST + n) = make_float2(d[nt][0], d[nt][1]);
            if (r1 < NTOK)
                *reinterpret_cast<float2*>(O + r1 * ST + n) = make_float2(d[nt][2], d[nt][3]);
        }
    }
}

// ---- cattn via MMA (6 warps), K=t padded to 64, both operands zeroed -------
__device__ __forceinline__ void cattn_mma(const float* QS, const float* KS,
                                          float* CAT, const float* NQ, const float* NK,
                                          int warp, int lane)
{
    if (warp >= 6) return;
    const int h = warp >> 1, mt = warp & 1;
    const int ch = h * HDIM, m0 = mt * 16;
    const int gid = lane >> 2, tig = lane & 3;
    float d[4][4];
    #pragma unroll
    for (int i = 0; i < 4; i++) { d[i][0] = d[i][1] = d[i][2] = d[i][3] = 0.f; }
    #pragma unroll
    for (int kc = 0; kc < 4; kc++) {
        const int k0 = 2 * (kc * 8 + tig);
        const int k1 = k0 + 1, k2 = k0 + 8, k3 = k0 + 9;
        const int ca = ch + m0 + gid;
        float a00 = (k0 < NTOK) ? KS[k0 * ST + ca] : 0.f;
        float a01 = (k1 < NTOK) ? KS[k1 * ST + ca] : 0.f;
        float a10 = (k0 < NTOK) ? KS[k0 * ST + ca + 8] : 0.f;
        float a11 = (k1 < NTOK) ? KS[k1 * ST + ca + 8] : 0.f;
        float a20 = (k2 < NTOK) ? KS[k2 * ST + ca] : 0.f;
        float a21 = (k3 < NTOK) ? KS[k3 * ST + ca] : 0.f;
        float a30 = (k2 < NTOK) ? KS[k2 * ST + ca + 8] : 0.f;
        float a31 = (k3 < NTOK) ? KS[k3 * ST + ca + 8] : 0.f;
        uint32_t a0h, a0l, a1h, a1l, a2h, a2l, a3h, a3l;
        split2(make_float2(a00, a01), a0h, a0l);
        split2(make_float2(a10, a11), a1h, a1l);
        split2(make_float2(a20, a21), a2h, a2l);
        split2(make_float2(a30, a31), a3h, a3l);
        #pragma unroll
        for (int nt = 0; nt < 4; nt++) {
            const int ce = ch + nt * 8 + gid;
            float b00 = (k0 < NTOK) ? QS[k0 * ST + ce] : 0.f;
            float b01 = (k1 < NTOK) ? QS[k1 * ST + ce] : 0.f;
            float b10 = (k2 < NTOK) ? QS[k2 * ST + ce] : 0.f;
            float b11 = (k3 < NTOK) ? QS[k3 * ST + ce] : 0.f;
            uint32_t b0h, b0l, b1h, b1l;
            split2(make_float2(b00, b01), b0h, b0l);
            split2(make_float2(b10, b11), b1h, b1l);
            mma16(d[nt], a0h, a1h, a2h, a3h, b0h, b1h);
            mma16(d[nt], a0h, a1h, a2h, a3h, b0l, b1l);
            mma16(d[nt], a0l, a1l, a2l, a3l, b0h, b1h);
        }
    }
    const int r0 = m0 + gid, r1 = r0 + 8;
    const float sk0 = NK[ch + r0] * SCALEF;
    const float sk1 = NK[ch + r1] * SCALEF;
    float* C0 = CAT + h * 1088 + r0 * CST;
    float* C1 = CAT + h * 1088 + r1 * CST;
    #pragma unroll
    for (int nt = 0; nt < 4; nt++) {
        int e0 = nt * 8 + tig * 2;
        float q0 = NQ[ch + e0], q1 = NQ[ch + e0 + 1];
        C0[e0]     = d[nt][0] * sk0 * q0;
        C0[e0 + 1] = d[nt][1] * sk0 * q1;
        C1[e0]     = d[nt][2] * sk1 * q0;
        C1[e0 + 1] = d[nt][3] * sk1 * q1;
    }
}

// ---- xc via MMA: 12 slots over 8 warps --------------------------------------
__device__ __forceinline__ void xc_mma(const float* CAT, const float* V, float* O,
                                       int warp, int lane)
{
    const int gid = lane >> 2, tig = lane & 3;
    for (int slot = warp; slot < 12; slot += 8) {
        const int h = slot >> 2, mt = slot & 3;
        const int ch = h * HDIM, m0 = mt * 16;
        float d[4][4];
        #pragma unroll
        for (int i = 0; i < 4; i++) { d[i][0] = d[i][1] = d[i][2] = d[i][3] = 0.f; }
        const float* Ar0 = V + (m0 + gid) * ST + ch;
        const float* Ar1 = Ar0 + 8 * ST;
        #pragma unroll
        for (int kc = 0; kc < 2; kc++) {
            const int kp = kc * 8 + tig;
            uint32_t a0h, a0l, a1h, a1l, a2h, a2l, a3h, a3l;
            split2(*reinterpret_cast<const float2*>(Ar0 + 2 * kp), a0h, a0l);
            split2(*reinterpret_cast<const float2*>(Ar1 + 2 * kp), a1h, a1l);
            split2(*reinterpret_cast<const float2*>(Ar0 + 2 * kp + 8), a2h, a2l);
            split2(*reinterpret_cast<const float2*>(Ar1 + 2 * kp + 8), a3h, a3l);
            #pragma unroll
            for (int nt = 0; nt < 4; nt++) {
                const float* Br = CAT + h * 1088 + (nt * 8 + gid) * CST;
                uint32_t b0h, b0l, b1h, b1l;
                split2(*reinterpret_cast<const float2*>(Br + 2 * kp), b0h, b0l);
                split2(*reinterpret_cast<const float2*>(Br + 2 * kp + 8), b1h, b1l);
                mma16(d[nt], a0h, a1h, a2h, a3h, b0h, b1h);
                mma16(d[nt], a0h, a1h, a2h, a3h, b0l, b1l);
                mma16(d[nt], a0l, a1l, a2l, a3l, b0h, b1h);
            }
        }
        const int r0 = m0 + gid, r1 = r0 + 8;
        #pragma unroll
        for (int nt = 0; nt < 4; nt++) {
            int n = ch + nt * 8 + tig * 2;
            if (r0 < NTOK)
                *reinterpret_cast<float2*>(O + r0 * ST + n) = make_float2(d[nt][0], d[nt][1]);
            if (r1 < NTOK)
                *reinterpret_cast<float2*>(O + r1 * ST + n) = make_float2(d[nt][2], d[nt][3]);
        }
    }
}

// ---- depthwise 3x3 conv, 4ch x 5tok per thread (240 active) ----------------
__device__ __forceinline__ void dwconv5(const float* In, const float* __restrict__ Wc,
                                        float* Out, int tid, int mode)
{
    if (tid >= 240) return;
    const int c0 = (tid / 10) * 4, t0 = (tid % 10) * 5;
    u64 wc[9][2];
    #pragma unroll
    for (int s = 0; s < 9; s++) {
        const ulonglong2* wp = reinterpret_cast<const ulonglong2*>(Wc + s * 96 + c0);
        ulonglong2 w = *wp;
        wc[s][0] = w.x; wc[s][1] = w.y;
    }
    #pragma unroll
    for (int tt = 0; tt < 5; tt++) {
        int t = t0 + tt;
        if (t >= NTOK) break;
        int r = t / 7, cc = t % 7;
        u64 a0 = 0ULL, a1 = 0ULL;
        #pragma unroll
        for (int dr = 0; dr < 3; dr++) {
            int rr = r + dr - 1;
            if (rr < 0 || rr > 6) continue;
            #pragma unroll
            for (int dc = 0; dc < 3; dc++) {
                int c2 = cc + dc - 1;
                if (c2 < 0 || c2 > 6) continue;
                const float* vp = In + (rr * 7 + c2) * ST + c0;
                fma2(a0, lds64(vp), wc[dr * 3 + dc][0]);
                fma2(a1, lds64(vp + 2), wc[dr * 3 + dc][1]);
            }
        }
        float2 p0 = unp(a0), p1 = unp(a1);
        float* o = Out + t * ST + c0;
        if (mode == 0) {
            o[0] = 0.5f * p0.x * (1.f + erff(p0.x * 0.70710678118654752f));
            o[1] = 0.5f * p0.y * (1.f + erff(p0.y * 0.70710678118654752f));
            o[2] = 0.5f * p1.x * (1.f + erff(p1.x * 0.70710678118654752f));
            o[3] = 0.5f * p1.y * (1.f + erff(p1.y * 0.70710678118654752f));
        } else {
            o[0] += p0.x; o[1] += p0.y; o[2] += p1.x; o[3] += p1.y;
        }
    }
}

__global__ __launch_bounds__(NTHR, 2) void winattn_kernel(
    const float* __restrict__ x,
    const float* __restrict__ rpb_table,
    const float* __restrict__ bq,  const float* __restrict__ bk,
    const float* __restrict__ bv,  const float* __restrict__ b_ps,
    const float* __restrict__ b_pc,
    const float* __restrict__ conv1, const float* __restrict__ conv2,
    const float* __restrict__ b_proj,
    float* __restrict__ out)
{
    extern __shared__ float sm[];
    float* A   = sm + OFF_A;      // x -> xc
    float* Bb  = sm + OFF_B;      // q -> sp -> ks -> conv1out
    float* Cc  = sm + OFF_C;      // k -> spat
    float* Dd  = sm + OFF_D;      // v
    float* Ee  = sm + OFF_E;      // scores (spans E+CAT) -> qs -> out_c/spec
    float* RPB = sm + OFF_RPB;
    float* NQ  = sm + OFF_NQ;
    float* NK  = sm + OFF_NK;
    float* CAT = sm + OFF_CAT;

    const int tid  = threadIdx.x;
    const int blk  = blockIdx.x;
    const int warp = tid >> 5, lane = tid & 31;

    {
        const float4* xg4 = reinterpret_cast<const float4*>(x + (size_t)blk * (NTOK * NCH));
        for (int i4 = tid; i4 < NTOK * 24; i4 += NTHR) {
            float4 v = xg4[i4];
            int t = i4 / 24, c = (i4 % 24) * 4;
            float* p = A + t * ST + c;
            p[0] = v.x; p[1] = v.y; p[2] = v.z; p[3] = v.w;
        }
        for (int i = tid; i < 507; i += NTHR) RPB[i] = rpb_table[i];
    }
    __syncthreads();

    // ---- ph1: {q (warps 0-3) | k (warps 4-7)} with B-frag reuse ----
    if (warp < 4) gemm2_bf16(A, 0 * FRAG_PER_G, bq, Bb, warp, lane);
    else          gemm2_bf16(A, 1 * FRAG_PER_G, bk, Cc, warp - 4, lane);
    __syncthreads();

    // ---- ph2: {v (warps 0-3) | scores all heads (warps 4-7)} ----
    if (warp < 4) gemm2_bf16(A, 2 * FRAG_PER_G, bv, Dd, warp, lane);
    else          scores_mma(Bb, Cc, Ee, RPB, warp - 4, 4, lane);
    __syncthreads();

    // ---- ph3: softmax, 147 rows over 8 warps ----
    for (int r = warp; r < 3 * NTOK; r += 8) {
        float* row = Ee + (r / NTOK) * SCRH + (r % NTOK) * AST;
        float e1 = row[lane];
        bool hi = (lane + 32) < NTOK;
        float e2 = hi ? row[lane + 32] : -3.4e38f;
        float m = fmaxf(e1, e2);
        #pragma unroll
        for (int o = 16; o > 0; o >>= 1) m = fmaxf(m, __shfl_xor_sync(0xffffffffu, m, o));
        float p1 = __expf(e1 - m);
        float p2 = hi ? __expf(e2 - m) : 0.f;
        float s = p1 + p2;
        #pragma unroll
        for (int o = 16; o > 0; o >>= 1) s += __shfl_xor_sync(0xffffffffu, s, o);
        float inv = 1.f / s;
        row[lane] = p1 * inv;
        if (hi) row[lane + 32] = p2 * inv;
        if (lane == 0) row[NTOK] = 0.f;
    }
    __syncthreads();

    // ---- ph4: attn@V all heads -> Bb ----
    attnv_mma(Ee, Dd, Bb, warp, lane);
    __syncthreads();

    // ---- ph5: {spatial = sp @ w_ps -> C (w0-3)} | {qs = x @ wq_sp -> E (w4-7)} ----
    if (warp < 4) gemm2_bf16(Bb, 3 * FRAG_PER_G, b_ps, Cc, warp, lane);
    else          gemm2_bf16(A, 4 * FRAG_PER_G, 0, Ee, warp - 4, lane);
    __syncthreads();

    // ---- ph6: ks = x @ wk_sp -> B (8 warps) ----
    gemm_bf16(A, 5 * FRAG_PER_G, 0, Bb, warp, lane);
    __syncthreads();

    // ---- ph7: inverse L2 norms ----
    if (tid < 96) {
        float s = 0.f;
        for (int t = 0; t < NTOK; t++) { float v = Ee[t * ST + tid]; s += v * v; }
        NQ[tid] = rsqrtf(fmaxf(s, 1e-24f));
    } else if (tid < 192) {
        int c = tid - 96;
        float s = 0.f;
        for (int t = 0; t < NTOK; t++) { float v = Bb[t * ST + c]; s += v * v; }
        NK[c] = rsqrtf(fmaxf(s, 1e-24f));
    }
    __syncthreads();

    // ---- ph8: cattn raw + normalize (MMA) ----
    cattn_mma(Ee, Bb, CAT, NQ, NK, warp, lane);
    __syncthreads();
    // ---- ph9: cattn softmax ----
    for (int rid = warp; rid < 96; rid += 8) {
        float* row = CAT + (rid >> 5) * 1088 + (rid & 31) * CST;
        float e = row[lane];
        float m = e;
        #pragma unroll
        for (int o = 16; o > 0; o >>= 1) m = fmaxf(m, __shfl_xor_sync(0xffffffffu, m, o));
        float p = __expf(e - m);
        float s = p;
        #pragma unroll
        for (int o = 16; o > 0; o >>= 1) s += __shfl_xor_sync(0xffffffffu, s, o);
        row[lane] = p * (1.f / s);
    }
    __syncthreads();

    // ---- ph10: xc = cattn @ v -> A ----
    xc_mma(CAT, Dd, A, warp, lane);
    __syncthreads();

    // ---- ph11: out_c = xc @ w_pc -> E (8 warps) then conv1(v)+GELU -> B ----
    gemm_bf16(A, 6 * FRAG_PER_G, b_pc, Ee, warp, lane);
    dwconv5(Dd, conv1, Bb, tid, 0);
    __syncthreads();

    // ---- ph12: conv2(gelu) -> E += ----
    dwconv5(Bb, conv2, Ee, tid, 1);
    __syncthreads();

    // ---- ph13: final projection (warps 0-3, B-frag reuse) ----
    if (warp < 4)
        proj2_bf16(Cc, Ee, b_proj, out + (size_t)blk * (NTOK * NCH), warp, lane);
}

extern "C" void kernel_launch(void* const* d_in, const int* in_sizes, int n_in,
                              void* d_out, int out_size)
{
    const float* x      = (const float*)d_in[0];
    const float* rpb    = (const float*)d_in[1];
    const float* wq     = (const float*)d_in[2];
    const float* bq     = (const float*)d_in[3];
    const float* wk     = (const float*)d_in[4];
    const float* bk     = (const float*)d_in[5];
    const float* wv     = (const float*)d_in[6];
    const float* bv     = (const float*)d_in[7];
    const float* w_ps   = (const float*)d_in[8];
    const float* b_ps   = (const float*)d_in[9];
    const float* wq_sp  = (const float*)d_in[10];
    const float* wk_sp  = (const float*)d_in[11];
    const float* w_pc   = (const float*)d_in[12];
    const float* b_pc   = (const float*)d_in[13];
    const float* conv1  = (const float*)d_in[14];
    const float* conv2  = (const float*)d_in[15];
    const float* w_proj = (const float*)d_in[16];
    const float* b_proj = (const float*)d_in[17];
    float* out = (float*)d_out;

    int nwin = in_sizes[0] / (NTOK * NCH);

    prep_weights<<<(NFRAG + 255) / 256, 256>>>(wq, wk, wv, w_ps, wq_sp, wk_sp, w_pc, w_proj);

    cudaFuncSetAttribute(winattn_kernel,
                         cudaFuncAttributeMaxDynamicSharedMemorySize, SMEM_BYTES);
    winattn_kernel<<<nwin, NTHR, SMEM_BYTES>>>(
        x, rpb, bq, bk, bv, b_ps, b_pc, conv1, conv2, b_proj, out);
}

// round 13
// speedup vs baseline: 1.0969x; 1.0123x over previous
#include <cuda_runtime.h>
#include <math.h>
#include <stdint.h>

// ---------------------------------------------------------------------------
// WindowAttention fused kernel, round 13 (base R12):
//  - x stored PRE-SPLIT (packed bf16x2 hi/lo planes) at load: q,k,v,qs,ks
//    GEMMs read A-fragments with plain LDS.32, no per-read conversion
//  - q,k written split from their GEMM epilogue: scores phase conversion-free
//  - gemm2 B-frag reuse, overlapped v|scores, merged softmax/attnv (R12)
// ---------------------------------------------------------------------------

#define NTOK   49
#define NCH    96
#define NHEADS 3
#define HDIM   32
#define ST     100
#define PST    50                          // packed bf16x2 row stride (words)
#define AST    50
#define CST    34
#define SCALEF 0.17677669529663687f
#define NTHR   256

#define BUF     (NTOK*ST)                  // 4900
#define OFF_A   0
#define OFF_B   (OFF_A + BUF)
#define OFF_C   (OFF_B + BUF)
#define OFF_D   (OFF_C + BUF)
#define OFF_RPB (OFF_D + BUF)              // 508
#define OFF_NQ  (OFF_RPB + 508)            // 96
#define OFF_NK  (OFF_NQ + 96)              // 96
#define OFF_E   (OFF_NK + 96)              // 4900 (scores span E+CAT)
#define OFF_CAT (OFF_E + BUF)              // 3264
#define SMEM_FLOATS (OFF_CAT + 3264)
#define SMEM_BYTES  (SMEM_FLOATS * 4)      // 113856

#define SCRH    2450

#define FRAG_PER_G 2304
#define PROJ_FBASE (7 * FRAG_PER_G)
#define NFRAG      (PROJ_FBASE + 12 * 12 * 32)

__device__ uint4 g_wpack[NFRAG];

typedef unsigned long long u64;

__device__ __forceinline__ void fma2(u64& d, u64 a, u64 b) {
    asm("fma.rn.f32x2 %0,%1,%2,%0;" : "+l"(d) : "l"(a), "l"(b));
}
__device__ __forceinline__ float2 unp(u64 a) {
    float2 r; asm("mov.b64 {%0,%1},%2;" : "=f"(r.x), "=f"(r.y) : "l"(a)); return r;
}
__device__ __forceinline__ u64 lds64(const float* p) {
    return *reinterpret_cast<const u64*>(p);
}
__device__ __forceinline__ uint32_t cvtbf2(float h, float l) {
    uint32_t r; asm("cvt.rn.bf16x2.f32 %0, %1, %2;" : "=r"(r) : "f"(h), "f"(l)); return r;
}
__device__ __forceinline__ float blo2f(uint32_t p) { return __uint_as_float(p << 16); }
__device__ __forceinline__ float bhi2f(uint32_t p) { return __uint_as_float(p & 0xFFFF0000u); }

__device__ __forceinline__ void mma16(float d[4],
                                      uint32_t a0, uint32_t a1, uint32_t a2, uint32_t a3,
                                      uint32_t b0, uint32_t b1) {
    asm volatile("mma.sync.aligned.m16n8k16.row.col.f32.bf16.bf16.f32 "
                 "{%0,%1,%2,%3}, {%4,%5,%6,%7}, {%8,%9}, {%0,%1,%2,%3};"
                 : "+f"(d[0]), "+f"(d[1]), "+f"(d[2]), "+f"(d[3])
                 : "r"(a0), "r"(a1), "r"(a2), "r"(a3), "r"(b0), "r"(b1));
}

__device__ __forceinline__ void split2(float2 p, uint32_t& h, uint32_t& l) {
    h = cvtbf2(p.y, p.x);
    l = cvtbf2(p.y - bhi2f(h), p.x - blo2f(h));
}

// ---------------- prologue: pack weight B-fragments in warp order -----------
__global__ void prep_weights(const float* __restrict__ wq, const float* __restrict__ wk,
                             const float* __restrict__ wv, const float* __restrict__ w_ps,
                             const float* __restrict__ wq_sp, const float* __restrict__ wk_sp,
                             const float* __restrict__ w_pc, const float* __restrict__ w_proj)
{
    int idx = blockIdx.x * 256 + threadIdx.x;
    if (idx >= NFRAG) return;
    const float* Wt[8] = {wq, wk, wv, w_ps, wq_sp, wk_sp, w_pc, w_proj};
    int g, r;
    if (idx < PROJ_FBASE) { g = idx / FRAG_PER_G; r = idx % FRAG_PER_G; }
    else                  { g = 7; r = idx - PROJ_FBASE; }
    int kc   = r / 384;
    int rem  = r % 384;
    int slot = rem / 32;
    int lane = rem % 32;
    int gid = lane >> 2, tig = lane & 3;
    int kp = kc * 8 + tig;
    int n  = slot * 8 + gid;
    const float* W = Wt[g];
    float x0 = W[(2 * kp) * 96 + n];
    float x1 = W[(2 * kp + 1) * 96 + n];
    float y0 = W[(2 * kp + 8) * 96 + n];
    float y1 = W[(2 * kp + 9) * 96 + n];
    uint32_t b0h, b0l, b1h, b1l;
    split2(make_float2(x0, x1), b0h, b0l);
    split2(make_float2(y0, y1), b1h, b1l);
    g_wpack[idx] = make_uint4(b0h, b1h, b0l, b1l);
}

// ---- gemm2s: pre-split A (Ah/Al), M=32 x N=48 per slot (sub in [0,4)) ------
// splitout=0: fp32 out (stride ST); splitout=1: packed hi/lo out (stride PST)
__device__ __forceinline__ void gemm2s(const uint32_t* Ah, const uint32_t* Al, int fbase,
                                       const float* __restrict__ bias,
                                       float* Os, uint32_t* Oh, uint32_t* Ol,
                                       int sub, int lane, int splitout)
{
    const int m0 = (sub >> 1) * 32;
    const int nh = sub & 1, n0 = nh * 48;
    const int gid = lane >> 2, tig = lane & 3;
    float d[2][6][4];
    #pragma unroll
    for (int m = 0; m < 2; m++)
        #pragma unroll
        for (int i = 0; i < 6; i++) { d[m][i][0] = d[m][i][1] = d[m][i][2] = d[m][i][3] = 0.f; }
    const int r0b = (m0 + gid) * PST, r1b = (m0 + gid + 8) * PST;
    const int r2b = (m0 + gid + 16) * PST, r3b = (m0 + gid + 24) * PST;
    #pragma unroll
    for (int kc = 0; kc < 6; kc++) {
        const int kp = kc * 8 + tig;
        uint32_t ah[2][4], al[2][4];
        ah[0][0] = Ah[r0b + kp];     al[0][0] = Al[r0b + kp];
        ah[0][1] = Ah[r1b + kp];     al[0][1] = Al[r1b + kp];
        ah[0][2] = Ah[r0b + kp + 4]; al[0][2] = Al[r0b + kp + 4];
        ah[0][3] = Ah[r1b + kp + 4]; al[0][3] = Al[r1b + kp + 4];
        ah[1][0] = Ah[r2b + kp];     al[1][0] = Al[r2b + kp];
        ah[1][1] = Ah[r3b + kp];     al[1][1] = Al[r3b + kp];
        ah[1][2] = Ah[r2b + kp + 4]; al[1][2] = Al[r2b + kp + 4];
        ah[1][3] = Ah[r3b + kp + 4]; al[1][3] = Al[r3b + kp + 4];
        const uint4* Bf = g_wpack + fbase + (kc * 12 + nh * 6) * 32 + lane;
        #pragma unroll
        for (int nt = 0; nt < 6; nt++) {
            uint4 w = Bf[nt * 32];
            #pragma unroll
            for (int m = 0; m < 2; m++) {
                mma16(d[m][nt], ah[m][0], ah[m][1], ah[m][2], ah[m][3], w.x, w.y);
                mma16(d[m][nt], ah[m][0], ah[m][1], ah[m][2], ah[m][3], w.z, w.w);
                mma16(d[m][nt], al[m][0], al[m][1], al[m][2], al[m][3], w.x, w.y);
            }
        }
    }
    #pragma unroll
    for (int m = 0; m < 2; m++) {
        const int r0 = m0 + m * 16 + gid, r1 = r0 + 8;
        #pragma unroll
        for (int nt = 0; nt < 6; nt++) {
            int n = n0 + nt * 8 + tig * 2;
            float bx = 0.f, by = 0.f;
            if (bias) { bx = bias[n]; by = bias[n + 1]; }
            if (splitout) {
                int w = n >> 1;
                if (r0 < NTOK) {
                    uint32_t h, l;
                    split2(make_float2(d[m][nt][0] + bx, d[m][nt][1] + by), h, l);
                    Oh[r0 * PST + w] = h; Ol[r0 * PST + w] = l;
                }
                if (r1 < NTOK) {
                    uint32_t h, l;
                    split2(make_float2(d[m][nt][2] + bx, d[m][nt][3] + by), h, l);
                    Oh[r1 * PST + w] = h; Ol[r1 * PST + w] = l;
                }
            } else {
                if (r0 < NTOK) { float* o = Os + r0 * ST + n; o[0] = d[m][nt][0] + bx; o[1] = d[m][nt][1] + by; }
                if (r1 < NTOK) { float* o = Os + r1 * ST + n; o[0] = d[m][nt][2] + bx; o[1] = d[m][nt][3] + by; }
            }
        }
    }
}

// ---- gemm_s8: pre-split A, 8 warps, M=16 tiles (for solo ks phase) ---------
__device__ __forceinline__ void gemm_s8(const uint32_t* Ah, const uint32_t* Al, int fbase,
                                        const float* __restrict__ bias, float* Os,
                                        int warp, int lane)
{
    const int m0 = (warp >> 1) * 16;
    const int nh = warp & 1, n0 = nh * 48;
    const int gid = lane >> 2, tig = lane & 3;
    float d[6][4];
    #pragma unroll
    for (int i = 0; i < 6; i++) { d[i][0] = d[i][1] = d[i][2] = d[i][3] = 0.f; }
    const int r0b = (m0 + gid) * PST, r1b = (m0 + gid + 8) * PST;
    #pragma unroll
    for (int kc = 0; kc < 6; kc++) {
        const int kp = kc * 8 + tig;
        uint32_t a0h = Ah[r0b + kp],     a0l = Al[r0b + kp];
        uint32_t a1h = Ah[r1b + kp],     a1l = Al[r1b + kp];
        uint32_t a2h = Ah[r0b + kp + 4], a2l = Al[r0b + kp + 4];
        uint32_t a3h = Ah[r1b + kp + 4], a3l = Al[r1b + kp + 4];
        const uint4* Bf = g_wpack + fbase + (kc * 12 + nh * 6) * 32 + lane;
        #pragma unroll
        for (int nt = 0; nt < 6; nt++) {
            uint4 w = Bf[nt * 32];
            mma16(d[nt], a0h, a1h, a2h, a3h, w.x, w.y);
            mma16(d[nt], a0h, a1h, a2h, a3h, w.z, w.w);
            mma16(d[nt], a0l, a1l, a2l, a3l, w.x, w.y);
        }
    }
    const int r0 = m0 + gid, r1 = m0 + gid + 8;
    #pragma unroll
    for (int nt = 0; nt < 6; nt++) {
        int n = n0 + nt * 8 + tig * 2;
        float bx = 0.f, by = 0.f;
        if (bias) { bx = bias[n]; by = bias[n + 1]; }
        if (r0 < NTOK) { float* o = Os + r0 * ST + n; o[0] = d[nt][0] + bx; o[1] = d[nt][1] + by; }
        if (r1 < NTOK) { float* o = Os + r1 * ST + n; o[0] = d[nt][2] + bx; o[1] = d[nt][3] + by; }
    }
}

// ---- gemm2 (fp32 A, split-in-loop) for sp@w_ps ------------------------------
__device__ __forceinline__ void gemm2_bf16(const float* Xs, int fbase,
                                           const float* __restrict__ bias, float* Os,
                                           int sub, int lane)
{
    const int m0 = (sub >> 1) * 32;
    const int nh = sub & 1, n0 = nh * 48;
    const int gid = lane >> 2, tig = lane & 3;
    float d[2][6][4];
    #pragma unroll
    for (int m = 0; m < 2; m++)
        #pragma unroll
        for (int i = 0; i < 6; i++) { d[m][i][0] = d[m][i][1] = d[m][i][2] = d[m][i][3] = 0.f; }
    const float* X0 = Xs + (m0 + gid) * ST;
    const float* X1 = Xs + (m0 + gid + 8) * ST;
    const float* X2 = Xs + (m0 + gid + 16) * ST;
    const float* X3 = Xs + (m0 + gid + 24) * ST;
    #pragma unroll
    for (int kc = 0; kc < 6; kc++) {
        const int kp = kc * 8 + tig;
        uint32_t ah[2][4], al[2][4];
        split2(*reinterpret_cast<const float2*>(X0 + 2 * kp),     ah[0][0], al[0][0]);
        split2(*reinterpret_cast<const float2*>(X1 + 2 * kp),     ah[0][1], al[0][1]);
        split2(*reinterpret_cast<const float2*>(X0 + 2 * kp + 8), ah[0][2], al[0][2]);
        split2(*reinterpret_cast<const float2*>(X1 + 2 * kp + 8), ah[0][3], al[0][3]);
        split2(*reinterpret_cast<const float2*>(X2 + 2 * kp),     ah[1][0], al[1][0]);
        split2(*reinterpret_cast<const float2*>(X3 + 2 * kp),     ah[1][1], al[1][1]);
        split2(*reinterpret_cast<const float2*>(X2 + 2 * kp + 8), ah[1][2], al[1][2]);
        split2(*reinterpret_cast<const float2*>(X3 + 2 * kp + 8), ah[1][3], al[1][3]);
        const uint4* Bf = g_wpack + fbase + (kc * 12 + nh * 6) * 32 + lane;
        #pragma unroll
        for (int nt = 0; nt < 6; nt++) {
            uint4 w = Bf[nt * 32];
            #pragma unroll
            for (int m = 0; m < 2; m++) {
                mma16(d[m][nt], ah[m][0], ah[m][1], ah[m][2], ah[m][3], w.x, w.y);
                mma16(d[m][nt], ah[m][0], ah[m][1], ah[m][2], ah[m][3], w.z, w.w);
                mma16(d[m][nt], al[m][0], al[m][1], al[m][2], al[m][3], w.x, w.y);
            }
        }
    }
    #pragma unroll
    for (int m = 0; m < 2; m++) {
        const int r0 = m0 + m * 16 + gid, r1 = r0 + 8;
        #pragma unroll
        for (int nt = 0; nt < 6; nt++) {
            int n = n0 + nt * 8 + tig * 2;
            float bx = 0.f, by = 0.f;
            if (bias) { bx = bias[n]; by = bias[n + 1]; }
            if (r0 < NTOK) { float* o = Os + r0 * ST + n; o[0] = d[m][nt][0] + bx; o[1] = d[m][nt][1] + by; }
            if (r1 < NTOK) { float* o = Os + r1 * ST + n; o[0] = d[m][nt][2] + bx; o[1] = d[m][nt][3] + by; }
        }
    }
}

// ---- R10-style 8-warp GEMM (fp32 A) for out_c ------------------------------
__device__ __forceinline__ void gemm_bf16(const float* Xs, int fbase,
                                          const float* __restrict__ bias, float* Os,
                                          int warp, int lane)
{
    const int m0 = (warp >> 1) * 16;
    const int nh = warp & 1;
    const int n0 = nh * 48;
    const int gid = lane >> 2, tig = lane & 3;
    float d[6][4];
    #pragma unroll
    for (int i = 0; i < 6; i++) { d[i][0] = d[i][1] = d[i][2] = d[i][3] = 0.f; }
    const float* Xr0 = Xs + (m0 + gid) * ST;
    const float* Xr1 = Xs + (m0 + gid + 8) * ST;
    #pragma unroll
    for (int kc = 0; kc < 6; kc++) {
        const int kp = kc * 8 + tig;
        uint32_t a0h, a0l, a1h, a1l, a2h, a2l, a3h, a3l;
        split2(*reinterpret_cast<const float2*>(Xr0 + 2 * kp), a0h, a0l);
        split2(*reinterpret_cast<const float2*>(Xr1 + 2 * kp), a1h, a1l);
        split2(*reinterpret_cast<const float2*>(Xr0 + 2 * kp + 8), a2h, a2l);
        split2(*reinterpret_cast<const float2*>(Xr1 + 2 * kp + 8), a3h, a3l);
        const uint4* Bf = g_wpack + fbase + (kc * 12 + nh * 6) * 32 + lane;
        #pragma unroll
        for (int nt = 0; nt < 6; nt++) {
            uint4 w = Bf[nt * 32];
            mma16(d[nt], a0h, a1h, a2h, a3h, w.x, w.y);
            mma16(d[nt], a0h, a1h, a2h, a3h, w.z, w.w);
            mma16(d[nt], a0l, a1l, a2l, a3l, w.x, w.y);
        }
    }
    const int r0 = m0 + gid, r1 = m0 + gid + 8;
    #pragma unroll
    for (int nt = 0; nt < 6; nt++) {
        int n = n0 + nt * 8 + tig * 2;
        float bx = 0.f, by = 0.f;
        if (bias) { bx = bias[n]; by = bias[n + 1]; }
        if (r0 < NTOK) { float* o = Os + r0 * ST + n; o[0] = d[nt][0] + bx; o[1] = d[nt][1] + by; }
        if (r1 < NTOK) { float* o = Os + r1 * ST + n; o[0] = d[nt][2] + bx; o[1] = d[nt][3] + by; }
    }
}

// ---- final projection with B-frag reuse (fp32 inputs) ----------------------
__device__ __forceinline__ void proj2_bf16(const float* Sa, const float* Sb,
                                           const float* __restrict__ bias,
                                           float* __restrict__ og, int sub, int lane)
{
    const int m0 = (sub >> 1) * 32;
    const int nh = sub & 1, n0 = nh * 48;
    const int gid = lane >> 2, tig = lane & 3;
    float d[2][6][4];
    #pragma unroll
    for (int m = 0; m < 2; m++)
        #pragma unroll
        for (int i = 0; i < 6; i++) { d[m][i][0] = d[m][i][1] = d[m][i][2] = d[m][i][3] = 0.f; }
    #pragma unroll
    for (int kc = 0; kc < 12; kc++) {
        const int kp = (kc % 6) * 8 + tig;
        const float* Xb = (kc < 6) ? Sa : Sb;
        const float* X0 = Xb + (m0 + gid) * ST;
        const float* X1 = X0 + 8 * ST;
        const float* X2 = X0 + 16 * ST;
        const float* X3 = X0 + 24 * ST;
        uint32_t ah[2][4], al[2][4];
        split2(*reinterpret_cast<const float2*>(X0 + 2 * kp),     ah[0][0], al[0][0]);
        split2(*reinterpret_cast<const float2*>(X1 + 2 * kp),     ah[0][1], al[0][1]);
        split2(*reinterpret_cast<const float2*>(X0 + 2 * kp + 8), ah[0][2], al[0][2]);
        split2(*reinterpret_cast<const float2*>(X1 + 2 * kp + 8), ah[0][3], al[0][3]);
        split2(*reinterpret_cast<const float2*>(X2 + 2 * kp),     ah[1][0], al[1][0]);
        split2(*reinterpret_cast<const float2*>(X3 + 2 * kp),     ah[1][1], al[1][1]);
        split2(*reinterpret_cast<const float2*>(X2 + 2 * kp + 8), ah[1][2], al[1][2]);
        split2(*reinterpret_cast<const float2*>(X3 + 2 * kp + 8), ah[1][3], al[1][3]);
        const uint4* Bf = g_wpack + PROJ_FBASE + (kc * 12 + nh * 6) * 32 + lane;
        #pragma unroll
        for (int nt = 0; nt < 6; nt++) {
            uint4 w = Bf[nt * 32];
            #pragma unroll
            for (int m = 0; m < 2; m++) {
                mma16(d[m][nt], ah[m][0], ah[m][1], ah[m][2], ah[m][3], w.x, w.y);
                mma16(d[m][nt], ah[m][0], ah[m][1], ah[m][2], ah[m][3], w.z, w.w);
                mma16(d[m][nt], al[m][0], al[m][1], al[m][2], al[m][3], w.x, w.y);
            }
        }
    }
    #pragma unroll
    for (int m = 0; m < 2; m++) {
        const int r0 = m0 + m * 16 + gid, r1 = r0 + 8;
        #pragma unroll
        for (int nt = 0; nt < 6; nt++) {
            int n = n0 + nt * 8 + tig * 2;
            float bx = bias[n], by = bias[n + 1];
            if (r0 < NTOK) {
                float2 v = make_float2(d[m][nt][0] + bx, d[m][nt][1] + by);
                *reinterpret_cast<float2*>(og + r0 * NCH + n) = v;
            }
            if (r1 < NTOK) {
                float2 v = make_float2(d[m][nt][2] + bx, d[m][nt][3] + by);
                *reinterpret_cast<float2*>(og + r1 * NCH + n) = v;
            }
        }
    }
}

// ---- scores from PRE-SPLIT q/k: conversion-free -----------------------------
__device__ __forceinline__ void scores_mma_s(const uint32_t* Qh, const uint32_t* Ql,
                                             const uint32_t* Kh, const uint32_t* Kl,
                                             float* SC, const float* RPB,
                                             int slot0, int stride, int lane)
{
    const int gid = lane >> 2, tig = lane & 3;
    for (int slot = slot0; slot < 24; slot += stride) {
        const int h = slot >> 3, q = slot & 7;
        const int m0 = (q >> 1) * 16, n0 = (q & 1) * 32;
        const int cw = h * 16;   // channel base in words (h*32/2)
        float* SCR = SC + h * SCRH;
        float d[4][4];
        #pragma unroll
        for (int i = 0; i < 4; i++) { d[i][0] = d[i][1] = d[i][2] = d[i][3] = 0.f; }
        const int q0b = (m0 + gid) * PST + cw, q1b = q0b + 8 * PST;
        #pragma unroll
        for (int kc = 0; kc < 2; kc++) {
            const int kp = kc * 8 + tig;
            uint32_t a0h = Qh[q0b + kp],     a0l = Ql[q0b + kp];
            uint32_t a1h = Qh[q1b + kp],     a1l = Ql[q1b + kp];
            uint32_t a2h = Qh[q0b + kp + 4], a2l = Ql[q0b + kp + 4];
            uint32_t a3h = Qh[q1b + kp + 4], a3l = Ql[q1b + kp + 4];
            #pragma unroll
            for (int nt = 0; nt < 4; nt++) {
                const int kb = (n0 + nt * 8 + gid) * PST + cw;
                uint32_t b0h = Kh[kb + kp],     b0l = Kl[kb + kp];
                uint32_t b1h = Kh[kb + kp + 4], b1l = Kl[kb + kp + 4];
                mma16(d[nt], a0h, a1h, a2h, a3h, b0h, b1h);
                mma16(d[nt], a0h, a1h, a2h, a3h, b0l, b1l);
                mma16(d[nt], a0l, a1l, a2l, a3l, b0h, b1h);
            }
        }
        const int r0 = m0 + gid, r1 = r0 + 8;
        const int i0r = r0 / 7, i0c = r0 % 7;
        const int i1r = r1 / 7, i1c = r1 % 7;
        #pragma unroll
        for (int nt = 0; nt < 4; nt++) {
            #pragma unroll
            for (int c = 0; c < 2; c++) {
                int j = n0 + nt * 8 + tig * 2 + c;
                if (j < NTOK) {
                    int jr = j / 7, jc = j % 7;
                    if (r0 < NTOK)
                        SCR[r0 * AST + j] = d[nt][c] * SCALEF
                            + RPB[((i0r - jr + 6) * 13 + (i0c - jc + 6)) * 3 + h];
                    if (r1 < NTOK)
                        SCR[r1 * AST + j] = d[nt][2 + c] * SCALEF
                            + RPB[((i1r - jr + 6) * 13 + (i1c - jc + 6)) * 3 + h];
                }
            }
        }
    }
}

// ---- attn@V (ALL heads): 24 slots over 8 warps ------------------------------
__device__ __forceinline__ void attnv_mma(const float* SC, const float* V,
                                          float* O, int warp, int lane)
{
    const int gid = lane >> 2, tig = lane & 3;
    for (int slot = warp; slot < 24; slot += 8) {
        const int h = slot >> 3, q = slot & 7;
        const int m0 = (q >> 1) * 16, n0 = (q & 1) * 16;
        const int ch0 = h * HDIM;
        const float* SCR = SC + h * SCRH;
        float d[2][4];
        #pragma unroll
        for (int i = 0; i < 2; i++) { d[i][0] = d[i][1] = d[i][2] = d[i][3] = 0.f; }
        const float* Pr0 = SCR + (m0 + gid) * AST;
        const float* Pr1 = Pr0 + 8 * AST;
        #pragma unroll
        for (int kc = 0; kc < 4; kc++) {
            const int k0 = 2 * (kc * 8 + tig);
            const int k2 = k0 + 8;
            uint32_t a0h = 0, a0l = 0, a1h = 0, a1l = 0;
            uint32_t a2h = 0, a2l = 0, a3h = 0, a3l = 0;
            if (k0 <= 48) {
                split2(*reinterpret_cast<const float2*>(Pr0 + k0), a0h, a0l);
                split2(*reinterpret_cast<const float2*>(Pr1 + k0), a1h, a1l);
            }
            if (k2 <= 48) {
                split2(*reinterpret_cast<const float2*>(Pr0 + k2), a2h, a2l);
                split2(*reinterpret_cast<const float2*>(Pr1 + k2), a3h, a3l);
            }
            #pragma unroll
            for (int nt = 0; nt < 2; nt++) {
                const int n = ch0 + n0 + nt * 8 + gid;
                uint32_t b0h, b0l, b1h, b1l;
                split2(make_float2(V[k0 * ST + n], V[(k0 + 1) * ST + n]), b0h, b0l);
                split2(make_float2(V[k2 * ST + n], V[(k2 + 1) * ST + n]), b1h, b1l);
                mma16(d[nt], a0h, a1h, a2h, a3h, b0h, b1h);
                mma16(d[nt], a0h, a1h, a2h, a3h, b0l, b1l);
                mma16(d[nt], a0l, a1l, a2l, a3l, b0h, b1h);
            }
        }
        const int r0 = m0 + gid, r1 = r0 + 8;
        #pragma unroll
        for (int nt = 0; nt < 2; nt++) {
            int n = ch0 + n0 + nt * 8 + tig * 2;
            if (r0 < NTOK)
                *reinterpret_cast<float2*>(O + r0 * ST + n) = make_float2(d[nt][0], d[nt][1]);
            if (r1 < NTOK)
                *reinterpret_cast<float2*>(O + r1 * ST + n) = make_float2(d[nt][2], d[nt][3]);
        }
    }
}

// ---- cattn via MMA (6 warps), K=t padded to 64, both operands zeroed -------
__device__ __forceinline__ void cattn_mma(const float* QS, const float* KS,
                                          float* CAT, const float* NQ, const float* NK,
                                          int warp, int lane)
{
    if (warp >= 6) return;
    const int h = warp >> 1, mt = warp & 1;
    const int ch = h * HDIM, m0 = mt * 16;
    const int gid = lane >> 2, tig = lane & 3;
    float d[4][4];
    #pragma unroll
    for (int i = 0; i < 4; i++) { d[i][0] = d[i][1] = d[i][2] = d[i][3] = 0.f; }
    #pragma unroll
    for (int kc = 0; kc < 4; kc++) {
        const int k0 = 2 * (kc * 8 + tig);
        const int k1 = k0 + 1, k2 = k0 + 8, k3 = k0 + 9;
        const int ca = ch + m0 + gid;
        float a00 = (k0 < NTOK) ? KS[k0 * ST + ca] : 0.f;
        float a01 = (k1 < NTOK) ? KS[k1 * ST + ca] : 0.f;
        float a10 = (k0 < NTOK) ? KS[k0 * ST + ca + 8] : 0.f;
        float a11 = (k1 < NTOK) ? KS[k1 * ST + ca + 8] : 0.f;
        float a20 = (k2 < NTOK) ? KS[k2 * ST + ca] : 0.f;
        float a21 = (k3 < NTOK) ? KS[k3 * ST + ca] : 0.f;
        float a30 = (k2 < NTOK) ? KS[k2 * ST + ca + 8] : 0.f;
        float a31 = (k3 < NTOK) ? KS[k3 * ST + ca + 8] : 0.f;
        uint32_t a0h, a0l, a1h, a1l, a2h, a2l, a3h, a3l;
        split2(make_float2(a00, a01), a0h, a0l);
        split2(make_float2(a10, a11), a1h, a1l);
        split2(make_float2(a20, a21), a2h, a2l);
        split2(make_float2(a30, a31), a3h, a3l);
        #pragma unroll
        for (int nt = 0; nt < 4; nt++) {
            const int ce = ch + nt * 8 + gid;
            float b00 = (k0 < NTOK) ? QS[k0 * ST + ce] : 0.f;
            float b01 = (k1 < NTOK) ? QS[k1 * ST + ce] : 0.f;
            float b10 = (k2 < NTOK) ? QS[k2 * ST + ce] : 0.f;
            float b11 = (k3 < NTOK) ? QS[k3 * ST + ce] : 0.f;
            uint32_t b0h, b0l, b1h, b1l;
            split2(make_float2(b00, b01), b0h, b0l);
            split2(make_float2(b10, b11), b1h, b1l);
            mma16(d[nt], a0h, a1h, a2h, a3h, b0h, b1h);
            mma16(d[nt], a0h, a1h, a2h, a3h, b0l, b1l);
            mma16(d[nt], a0l, a1l, a2l, a3l, b0h, b1h);
        }
    }
    const int r0 = m0 + gid, r1 = r0 + 8;
    const float sk0 = NK[ch + r0] * SCALEF;
    const float sk1 = NK[ch + r1] * SCALEF;
    float* C0 = CAT + h * 1088 + r0 * CST;
    float* C1 = CAT + h * 1088 + r1 * CST;
    #pragma unroll
    for (int nt = 0; nt < 4; nt++) {
        int e0 = nt * 8 + tig * 2;
        float q0 = NQ[ch + e0], q1 = NQ[ch + e0 + 1];
        C0[e0]     = d[nt][0] * sk0 * q0;
        C0[e0 + 1] = d[nt][1] * sk0 * q1;
        C1[e0]     = d[nt][2] * sk1 * q0;
        C1[e0 + 1] = d[nt][3] * sk1 * q1;
    }
}

// ---- xc via MMA: 12 slots over 8 warps --------------------------------------
__device__ __forceinline__ void xc_mma(const float* CAT, const float* V, float* O,
                                       int warp, int lane)
{
    const int gid = lane >> 2, tig = lane & 3;
    for (int slot = warp; slot < 12; slot += 8) {
        const int h = slot >> 2, mt = slot & 3;
        const int ch = h * HDIM, m0 = mt * 16;
        float d[4][4];
        #pragma unroll
        for (int i = 0; i < 4; i++) { d[i][0] = d[i][1] = d[i][2] = d[i][3] = 0.f; }
        const float* Ar0 = V + (m0 + gid) * ST + ch;
        const float* Ar1 = Ar0 + 8 * ST;
        #pragma unroll
        for (int kc = 0; kc < 2; kc++) {
            const int kp = kc * 8 + tig;
            uint32_t a0h, a0l, a1h, a1l, a2h, a2l, a3h, a3l;
            split2(*reinterpret_cast<const float2*>(Ar0 + 2 * kp), a0h, a0l);
            split2(*reinterpret_cast<const float2*>(Ar1 + 2 * kp), a1h, a1l);
            split2(*reinterpret_cast<const float2*>(Ar0 + 2 * kp + 8), a2h, a2l);
            split2(*reinterpret_cast<const float2*>(Ar1 + 2 * kp + 8), a3h, a3l);
            #pragma unroll
            for (int nt = 0; nt < 4; nt++) {
                const float* Br = CAT + h * 1088 + (nt * 8 + gid) * CST;
                uint32_t b0h, b0l, b1h, b1l;
                split2(*reinterpret_cast<const float2*>(Br + 2 * kp), b0h, b0l);
                split2(*reinterpret_cast<const float2*>(Br + 2 * kp + 8), b1h, b1l);
                mma16(d[nt], a0h, a1h, a2h, a3h, b0h, b1h);
                mma16(d[nt], a0h, a1h, a2h, a3h, b0l, b1l);
                mma16(d[nt], a0l, a1l, a2l, a3l, b0h, b1h);
            }
        }
        const int r0 = m0 + gid, r1 = r0 + 8;
        #pragma unroll
        for (int nt = 0; nt < 4; nt++) {
            int n = ch + nt * 8 + tig * 2;
            if (r0 < NTOK)
                *reinterpret_cast<float2*>(O + r0 * ST + n) = make_float2(d[nt][0], d[nt][1]);
            if (r1 < NTOK)
                *reinterpret_cast<float2*>(O + r1 * ST + n) = make_float2(d[nt][2], d[nt][3]);
        }
    }
}

// ---- depthwise 3x3 conv, 4ch x 5tok per thread (240 active) ----------------
__device__ __forceinline__ void dwconv5(const float* In, const float* __restrict__ Wc,
                                        float* Out, int tid, int mode)
{
    if (tid >= 240) return;
    const int c0 = (tid / 10) * 4, t0 = (tid % 10) * 5;
    u64 wc[9][2];
    #pragma unroll
    for (int s = 0; s < 9; s++) {
        const ulonglong2* wp = reinterpret_cast<const ulonglong2*>(Wc + s * 96 + c0);
        ulonglong2 w = *wp;
        wc[s][0] = w.x; wc[s][1] = w.y;
    }
    #pragma unroll
    for (int tt = 0; tt < 5; tt++) {
        int t = t0 + tt;
        if (t >= NTOK) break;
        int r = t / 7, cc = t % 7;
        u64 a0 = 0ULL, a1 = 0ULL;
        #pragma unroll
        for (int dr = 0; dr < 3; dr++) {
            int rr = r + dr - 1;
            if (rr < 0 || rr > 6) continue;
            #pragma unroll
            for (int dc = 0; dc < 3; dc++) {
                int c2 = cc + dc - 1;
                if (c2 < 0 || c2 > 6) continue;
                const float* vp = In + (rr * 7 + c2) * ST + c0;
                fma2(a0, lds64(vp), wc[dr * 3 + dc][0]);
                fma2(a1, lds64(vp + 2), wc[dr * 3 + dc][1]);
            }
        }
        float2 p0 = unp(a0), p1 = unp(a1);
        float* o = Out + t * ST + c0;
        if (mode == 0) {
            o[0] = 0.5f * p0.x * (1.f + erff(p0.x * 0.70710678118654752f));
            o[1] = 0.5f * p0.y * (1.f + erff(p0.y * 0.70710678118654752f));
            o[2] = 0.5f * p1.x * (1.f + erff(p1.x * 0.70710678118654752f));
            o[3] = 0.5f * p1.y * (1.f + erff(p1.y * 0.70710678118654752f));
        } else {
            o[0] += p0.x; o[1] += p0.y; o[2] += p1.x; o[3] += p1.y;
        }
    }
}

__global__ __launch_bounds__(NTHR, 2) void winattn_kernel(
    const float* __restrict__ x,
    const float* __restrict__ rpb_table,
    const float* __restrict__ bq,  const float* __restrict__ bk,
    const float* __restrict__ bv,  const float* __restrict__ b_ps,
    const float* __restrict__ b_pc,
    const float* __restrict__ conv1, const float* __restrict__ conv2,
    const float* __restrict__ b_proj,
    float* __restrict__ out)
{
    extern __shared__ float sm[];
    // A region: x split (Xh/Xl, 2450 words each) -> later fp32 xc
    uint32_t* Xh = reinterpret_cast<uint32_t*>(sm + OFF_A);
    uint32_t* Xl = Xh + 2450;
    float*    Axc = sm + OFF_A;
    // B region: q split -> fp32 sp -> fp32 ks -> conv1out
    uint32_t* Qh = reinterpret_cast<uint32_t*>(sm + OFF_B);
    uint32_t* Ql = Qh + 2450;
    float*    Bb = sm + OFF_B;
    // C region: k split -> fp32 spatial
    uint32_t* Kh = reinterpret_cast<uint32_t*>(sm + OFF_C);
    uint32_t* Kl = Kh + 2450;
    float*    Cc = sm + OFF_C;
    float* Dd  = sm + OFF_D;
    float* Ee  = sm + OFF_E;
    float* RPB = sm + OFF_RPB;
    float* NQ  = sm + OFF_NQ;
    float* NK  = sm + OFF_NK;
    float* CAT = sm + OFF_CAT;

    const int tid  = threadIdx.x;
    const int blk  = blockIdx.x;
    const int warp = tid >> 5, lane = tid & 31;

    // ---- load x and split to bf16 hi/lo at once ----
    {
        const float4* xg4 = reinterpret_cast<const float4*>(x + (size_t)blk * (NTOK * NCH));
        for (int i4 = tid; i4 < NTOK * 24; i4 += NTHR) {
            float4 v = xg4[i4];
            int t = i4 / 24, p = (i4 % 24) * 2;
            uint32_t h0, l0, h1, l1;
            split2(make_float2(v.x, v.y), h0, l0);
            split2(make_float2(v.z, v.w), h1, l1);
            Xh[t * PST + p] = h0;     Xl[t * PST + p] = l0;
            Xh[t * PST + p + 1] = h1; Xl[t * PST + p + 1] = l1;
        }
        for (int i = tid; i < 507; i += NTHR) RPB[i] = rpb_table[i];
    }
    __syncthreads();

    // ---- ph1: {q (w0-3) | k (w4-7)}, split-A in, SPLIT out ----
    if (warp < 4) gemm2s(Xh, Xl, 0 * FRAG_PER_G, bq, 0, Qh, Ql, warp, lane, 1);
    else          gemm2s(Xh, Xl, 1 * FRAG_PER_G, bk, 0, Kh, Kl, warp - 4, lane, 1);
    __syncthreads();

    // ---- ph2: {v (w0-3, fp32 out) | scores all heads (w4-7, conversion-free)} ----
    if (warp < 4) gemm2s(Xh, Xl, 2 * FRAG_PER_G, bv, Dd, 0, 0, warp, lane, 0);
    else          scores_mma_s(Qh, Ql, Kh, Kl, Ee, RPB, warp - 4, 4, lane);
    __syncthreads();

    // ---- ph3: softmax, 147 rows over 8 warps ----
    for (int r = warp; r < 3 * NTOK; r += 8) {
        float* row = Ee + (r / NTOK) * SCRH + (r % NTOK) * AST;
        float e1 = row[lane];
        bool hi = (lane + 32) < NTOK;
        float e2 = hi ? row[lane + 32] : -3.4e38f;
        float m = fmaxf(e1, e2);
        #pragma unroll
        for (int o = 16; o > 0; o >>= 1) m = fmaxf(m, __shfl_xor_sync(0xffffffffu, m, o));
        float p1 = __expf(e1 - m);
        float p2 = hi ? __expf(e2 - m) : 0.f;
        float s = p1 + p2;
        #pragma unroll
        for (int o = 16; o > 0; o >>= 1) s += __shfl_xor_sync(0xffffffffu, s, o);
        float inv = 1.f / s;
        row[lane] = p1 * inv;
        if (hi) row[lane + 32] = p2 * inv;
        if (lane == 0) row[NTOK] = 0.f;
    }
    __syncthreads();

    // ---- ph4: attn@V all heads -> Bb (fp32, q dead) ----
    attnv_mma(Ee, Dd, Bb, warp, lane);
    __syncthreads();

    // ---- ph5: {spatial = sp @ w_ps -> Cc (w0-3)} | {qs = xsplit @ wq_sp -> Ee (w4-7)} ----
    if (warp < 4) gemm2_bf16(Bb, 3 * FRAG_PER_G, b_ps, Cc, warp, lane);
    else          gemm2s(Xh, Xl, 4 * FRAG_PER_G, 0, Ee, 0, 0, warp - 4, lane, 0);
    __syncthreads();

    // ---- ph6: ks = xsplit @ wk_sp -> Bb (8 warps; sp consumed in ph5) ----
    gemm_s8(Xh, Xl, 5 * FRAG_PER_G, 0, Bb, warp, lane);
    __syncthreads();

    // ---- ph7: inverse L2 norms ----
    if (tid < 96) {
        float s = 0.f;
        for (int t = 0; t < NTOK; t++) { float v = Ee[t * ST + tid]; s += v * v; }
        NQ[tid] = rsqrtf(fmaxf(s, 1e-24f));
    } else if (tid < 192) {
        int c = tid - 96;
        float s = 0.f;
        for (int t = 0; t < NTOK; t++) { float v = Bb[t * ST + c]; s += v * v; }
        NK[c] = rsqrtf(fmaxf(s, 1e-24f));
    }
    __syncthreads();

    // ---- ph8: cattn raw + normalize ----
    cattn_mma(Ee, Bb, CAT, NQ, NK, warp, lane);
    __syncthreads();
    // ---- ph9: cattn softmax ----
    for (int rid = warp; rid < 96; rid += 8) {
        float* row = CAT + (rid >> 5) * 1088 + (rid & 31) * CST;
        float e = row[lane];
        float m = e;
        #pragma unroll
        for (int o = 16; o > 0; o >>= 1) m = fmaxf(m, __shfl_xor_sync(0xffffffffu, m, o));
        float p = __expf(e - m);
        float s = p;
        #pragma unroll
        for (int o = 16; o > 0; o >>= 1) s += __shfl_xor_sync(0xffffffffu, s, o);
        row[lane] = p * (1.f / s);
    }
    __syncthreads();

    // ---- ph10: xc = cattn @ v -> A region (fp32, x-split dead) ----
    xc_mma(CAT, Dd, Axc, warp, lane);
    __syncthreads();

    // ---- ph11: out_c = xc @ w_pc -> Ee (8 warps) + conv1(v)+GELU -> Bb ----
    gemm_bf16(Axc, 6 * FRAG_PER_G, b_pc, Ee, warp, lane);
    dwconv5(Dd, conv1, Bb, tid, 0);
    __syncthreads();

    // ---- ph12: conv2(gelu) -> Ee += ----
    dwconv5(Bb, conv2, Ee, tid, 1);
    __syncthreads();

    // ---- ph13: final projection (warps 0-3) ----
    if (warp < 4)
        proj2_bf16(Cc, Ee, b_proj, out + (size_t)blk * (NTOK * NCH), warp, lane);
}

extern "C" void kernel_launch(void* const* d_in, const int* in_sizes, int n_in,
                              void* d_out, int out_size)
{
    const float* x      = (const float*)d_in[0];
    const float* rpb    = (const float*)d_in[1];
    const float* wq     = (const float*)d_in[2];
    const float* bq     = (const float*)d_in[3];
    const float* wk     = (const float*)d_in[4];
    const float* bk     = (const float*)d_in[5];
    const float* wv     = (const float*)d_in[6];
    const float* bv     = (const float*)d_in[7];
    const float* w_ps   = (const float*)d_in[8];
    const float* b_ps   = (const float*)d_in[9];
    const float* wq_sp  = (const float*)d_in[10];
    const float* wk_sp  = (const float*)d_in[11];
    const float* w_pc   = (const float*)d_in[12];
    const float* b_pc   = (const float*)d_in[13];
    const float* conv1  = (const float*)d_in[14];
    const float* conv2  = (const float*)d_in[15];
    const float* w_proj = (const float*)d_in[16];
    const float* b_proj = (const float*)d_in[17];
    float* out = (float*)d_out;

    int nwin = in_sizes[0] / (NTOK * NCH);

    prep_weights<<<(NFRAG + 255) / 256, 256>>>(wq, wk, wv, w_ps, wq_sp, wk_sp, w_pc, w_proj);

    cudaFuncSetAttribute(winattn_kernel,
                         cudaFuncAttributeMaxDynamicSharedMemorySize, SMEM_BYTES);
    winattn_kernel<<<nwin, NTHR, SMEM_BYTES>>>(
        x, rpb, bq, bk, bv, b_ps, b_pc, conv1, conv2, b_proj, out);
}